// round 8
// baseline (speedup 1.0000x reference)
#include <cuda_runtime.h>
#include <cuda_bf16.h>
#include <mma.h>
#include <cstdint>

using namespace nvcuda;

// ---------------------------------------------------------------------------
// Problem constants
// ---------------------------------------------------------------------------
#define NN    2048         // nodes / batch
#define CC    16           // channels of x
#define HH    32
#define WW    32
#define HW    (HH*WW)      // 1024
#define FEAT  (CC*HW)      // 16384 floats per node
#define EMAX  16384

// Scratch (device globals; no allocation allowed in kernel_launch)
__device__ float g_neigh   [NN * CC * HW];   // 134 MB
__device__ float g_nonneigh[NN * CC * HW];   // 134 MB
__device__ float g_h1      [NN * 32 * HW];   // 268 MB
__device__ float g_h2      [NN * 32 * HW];   // 268 MB
__device__ int   g_edges64;
__device__ int   g_deg[NN];
__device__ int   g_off[NN + 1];
__device__ int   g_cur[NN];
__device__ int   g_adj[2 * EMAX];            // peer | (0x10000 if rel>0)

// Pre-split weights (bf16 hi/lo), K-ordered: k = (tap*(CIN/16)+cc)*16 + j,
// cin = cc*16+j. Row stride LDB (440 / 296) for conflict-free fragment loads.
__device__ __align__(16) __nv_bfloat16 g_b1hi[32 * 440];
__device__ __align__(16) __nv_bfloat16 g_b1lo[32 * 440];
__device__ __align__(16) __nv_bfloat16 g_b2hi[32 * 296];
__device__ __align__(16) __nv_bfloat16 g_b2lo[32 * 296];
__device__ __align__(16) __nv_bfloat16 g_b3hi[16 * 296];
__device__ __align__(16) __nv_bfloat16 g_b3lo[16 * 296];

// ---------------------------------------------------------------------------
// Edge decode + probe (dtype decided at runtime)
// ---------------------------------------------------------------------------
__device__ __forceinline__ void load_edge(const void* edges, int e,
                                          int& a, int& rel, int& b) {
    if (g_edges64) {
        const long long* p = (const long long*)edges;
        a = (int)p[3 * e + 0]; rel = (int)p[3 * e + 1]; b = (int)p[3 * e + 2];
    } else {
        const int* p = (const int*)edges;
        a = p[3 * e + 0]; rel = p[3 * e + 1]; b = p[3 * e + 2];
    }
}

__global__ void probe_dtype_kernel(const void* edges, int E) {
    const long long* e64 = (const long long*)edges;
    bool ok = true;
    int n = E < 8 ? E : 8;
    for (int i = 0; i < n; i++) {
        long long a   = e64[3 * i + 0];
        long long rel = e64[3 * i + 1];
        long long b   = e64[3 * i + 2];
        if (a < 0 || a >= NN || b < 0 || b >= NN ||
            !(rel == 1 || rel == -1)) { ok = false; break; }
    }
    g_edges64 = ok ? 1 : 0;
}

// ---------------------------------------------------------------------------
// CSR build
// ---------------------------------------------------------------------------
__global__ void csr_zero_kernel() {
    int i = blockIdx.x * blockDim.x + threadIdx.x;
    if (i < NN) g_deg[i] = 0;
}

__global__ void csr_count_kernel(const void* edges, int E) {
    int e = blockIdx.x * blockDim.x + threadIdx.x;
    if (e >= E) return;
    int a, rel, b;
    load_edge(edges, e, a, rel, b);
    if (a < 0 || a >= NN || b < 0 || b >= NN) return;
    atomicAdd(&g_deg[a], 1);
    atomicAdd(&g_deg[b], 1);
}

__global__ void __launch_bounds__(1024) csr_scan_kernel() {
    __shared__ int s[NN];
    int t = threadIdx.x;
    s[t]        = g_deg[t];
    s[t + 1024] = g_deg[t + 1024];
    __syncthreads();
    for (int d = 1; d < NN; d <<= 1) {
        int v0 = (t        >= d) ? s[t        - d] : 0;
        int v1 = (t + 1024 >= d) ? s[t + 1024 - d] : 0;
        __syncthreads();
        s[t]        += v0;
        s[t + 1024] += v1;
        __syncthreads();
    }
    g_off[t + 1]    = s[t];
    g_off[t + 1025] = s[t + 1024];
    if (t == 0) g_off[0] = 0;
    g_cur[t]        = (t == 0) ? 0 : s[t - 1];
    g_cur[t + 1024] = s[t + 1023];
}

__global__ void csr_fill_kernel(const void* edges, int E) {
    int e = blockIdx.x * blockDim.x + threadIdx.x;
    if (e >= E) return;
    int a, rel, b;
    load_edge(edges, e, a, rel, b);
    if (a < 0 || a >= NN || b < 0 || b >= NN) return;
    int flag = (rel > 0) ? 0x10000 : 0;
    int pa = atomicAdd(&g_cur[a], 1);
    g_adj[pa] = b | flag;
    int pb = atomicAdd(&g_cur[b], 1);
    g_adj[pb] = a | flag;
}

// ---------------------------------------------------------------------------
// Gather: block = (node n, feature half h). No atomics.
// ---------------------------------------------------------------------------
__global__ void __launch_bounds__(256) gather_kernel(
        const float* __restrict__ x,
        float* __restrict__ neigh,
        float* __restrict__ nonneigh) {
    const int n = blockIdx.x;
    const int h = blockIdx.y;
    const int t = threadIdx.x;

    float4 accN[8], accP[8];
#pragma unroll
    for (int j = 0; j < 8; j++) {
        accN[j] = make_float4(0.f, 0.f, 0.f, 0.f);
        accP[j] = make_float4(0.f, 0.f, 0.f, 0.f);
    }

    const int s = g_off[n], e = g_off[n + 1];
    const size_t base4h = (size_t)h * 2048;
    const float4* xb = (const float4*)x;

    for (int k = s; k < e; k++) {
        int ent = g_adj[k];
        int peer = ent & 0xFFFF;
        const float4* src = xb + (size_t)peer * (FEAT / 4) + base4h;
        if (ent & 0x10000) {
#pragma unroll
            for (int j = 0; j < 8; j++) {
                float4 v = src[t + 256 * j];
                accN[j].x += v.x; accN[j].y += v.y;
                accN[j].z += v.z; accN[j].w += v.w;
            }
        } else {
#pragma unroll
            for (int j = 0; j < 8; j++) {
                float4 v = src[t + 256 * j];
                accP[j].x += v.x; accP[j].y += v.y;
                accP[j].z += v.z; accP[j].w += v.w;
            }
        }
    }

    float4* dn = (float4*)neigh    + (size_t)n * (FEAT / 4) + base4h;
    float4* dp = (float4*)nonneigh + (size_t)n * (FEAT / 4) + base4h;
#pragma unroll
    for (int j = 0; j < 8; j++) {
        dn[t + 256 * j] = accN[j];
        dp[t + 256 * j] = accP[j];
    }
}

// ---------------------------------------------------------------------------
// Weight split prep: fp32 -> bf16 hi/lo, K-ordered rows of length LDB.
// ---------------------------------------------------------------------------
__global__ void prep_b_kernel(const float* __restrict__ w1,
                              const float* __restrict__ w2,
                              const float* __restrict__ w3) {
    int idx = blockIdx.x * blockDim.x + threadIdx.x;
    if (idx < 32 * 432) {
        int co = idx / 432, k = idx - co * 432;
        int ks = k >> 4, j = k & 15;
        int tap = ks / 3, cc = ks - tap * 3;
        float v = w1[(size_t)(co * 48 + cc * 16 + j) * 9 + tap];
        __nv_bfloat16 bh = __float2bfloat16(v);
        g_b1hi[co * 440 + k] = bh;
        g_b1lo[co * 440 + k] = __float2bfloat16(v - __bfloat162float(bh));
    }
    if (idx < 32 * 288) {
        int co = idx / 288, k = idx - co * 288;
        int ks = k >> 4, j = k & 15;
        int tap = ks >> 1, cc = ks & 1;
        float v = w2[(size_t)(co * 32 + cc * 16 + j) * 9 + tap];
        __nv_bfloat16 bh = __float2bfloat16(v);
        g_b2hi[co * 296 + k] = bh;
        g_b2lo[co * 296 + k] = __float2bfloat16(v - __bfloat162float(bh));
    }
    if (idx < 16 * 288) {
        int co = idx / 288, k = idx - co * 288;
        int ks = k >> 4, j = k & 15;
        int tap = ks >> 1, cc = ks & 1;
        float v = w3[(size_t)(co * 32 + cc * 16 + j) * 9 + tap];
        __nv_bfloat16 bh = __float2bfloat16(v);
        g_b3hi[co * 296 + k] = bh;
        g_b3lo[co * 296 + k] = __float2bfloat16(v - __bfloat162float(bh));
    }
}

// ---------------------------------------------------------------------------
// Conv 3x3 as 9 shifted GEMMs (wmma bf16, split precision, fp32 accum).
// Three INDEPENDENT accumulator sets (hh/lh/hl) so the 3 split-term MMAs per
// tile form independent dependency chains; merged elementwise in epilogue.
// ks loop fully unrolled -> compile-time tap/cc and smem offsets.
// ---------------------------------------------------------------------------
template <int CIN, int CINPAD, int COUT, int ROWS, int LDB, int KSTEPS>
__global__ void __launch_bounds__(256)
conv_shift_kernel(const float* __restrict__ src0,
                  const float* __restrict__ src1,
                  const float* __restrict__ src2,
                  int imgStride,
                  const __nv_bfloat16* __restrict__ Bhi,
                  const __nv_bfloat16* __restrict__ Blo,
                  const float* __restrict__ bias,
                  float* __restrict__ out) {
    extern __shared__ __align__(16) char smem[];
    constexpr int TIN = (ROWS + 2) * 34;
    constexpr int ASZ = TIN * CINPAD;
    constexpr int BSZ = COUT * LDB;
    constexpr int NT  = COUT / 16;
    constexpr int MT  = ROWS / 4;
    constexpr int NCC = CIN / 16;

    __nv_bfloat16* sA_hi = (__nv_bfloat16*)smem;
    __nv_bfloat16* sA_lo = sA_hi + ASZ;
    __nv_bfloat16* sB_hi = sA_lo + ASZ;
    __nv_bfloat16* sB_lo = sB_hi + BSZ;
    float*         sBias = (float*)(sB_lo + BSZ);

    const int tid  = threadIdx.x;
    const int wid  = tid >> 5;
    const int n    = blockIdx.x;
    const int row0 = blockIdx.y * ROWS;
    const int pix0 = row0 * 32;

    // ---- B copy (global bf16 -> smem), uint4 ----
    {
        const uint4* g1 = (const uint4*)Bhi;
        const uint4* g2 = (const uint4*)Blo;
        uint4* s1 = (uint4*)sB_hi;
        uint4* s2 = (uint4*)sB_lo;
        constexpr int NB = BSZ * 2 / 16;
        for (int i = tid; i < NB; i += 256) { s1[i] = g1[i]; s2[i] = g2[i]; }
    }
    // ---- bias tile ----
    for (int i = tid; i < 16 * COUT; i += 256) sBias[i] = bias[i & (COUT - 1)];

    // ---- A staging: fp32 -> bf16 hi/lo, [pixel][cin] ----
    const float* p0 = src0 + (size_t)n * imgStride;
    const float* p1 = src1 ? src1 + (size_t)n * imgStride : p0;
    const float* p2 = src2 ? src2 + (size_t)n * imgStride : p0;
    for (int idx = tid; idx < CIN * TIN; idx += 256) {
        int cin = idx / TIN;
        int pix = idx - cin * TIN;
        int r = pix / 34, c = pix - r * 34;
        int y = row0 + r - 1, x = c - 1;
        float v = 0.f;
        if ((unsigned)y < HH && (unsigned)x < WW) {
            const float* sp = (cin < 16) ? p0 : (cin < 32) ? p1 : p2;
            v = sp[(cin & 15) * HW + y * WW + x];
        }
        __nv_bfloat16 bh = __float2bfloat16(v);
        sA_hi[pix * CINPAD + cin] = bh;
        sA_lo[pix * CINPAD + cin] = __float2bfloat16(v - __bfloat162float(bh));
    }
    __syncthreads();

    wmma::fragment<wmma::accumulator, 16, 16, 16, float> acc_hh[MT][NT];
    wmma::fragment<wmma::accumulator, 16, 16, 16, float> acc_lh[MT][NT];
    wmma::fragment<wmma::accumulator, 16, 16, 16, float> acc_hl[MT][NT];
#pragma unroll
    for (int m2 = 0; m2 < MT; m2++)
#pragma unroll
        for (int n2 = 0; n2 < NT; n2++) {
            wmma::load_matrix_sync(acc_hh[m2][n2], sBias + n2 * 16, COUT,
                                   wmma::mem_row_major);
            wmma::fill_fragment(acc_lh[m2][n2], 0.f);
            wmma::fill_fragment(acc_hl[m2][n2], 0.f);
        }

#pragma unroll
    for (int ks = 0; ks < KSTEPS; ks++) {
        const int tap = ks / NCC;
        const int cc  = ks - tap * NCC;
        const int dy  = tap / 3;
        const int dx  = tap - dy * 3;

        wmma::fragment<wmma::matrix_b, 16, 16, 16, __nv_bfloat16,
                       wmma::col_major> b_hi[NT], b_lo[NT];
#pragma unroll
        for (int n2 = 0; n2 < NT; n2++) {
            wmma::load_matrix_sync(b_hi[n2], &sB_hi[n2 * 16 * LDB + ks * 16], LDB);
            wmma::load_matrix_sync(b_lo[n2], &sB_lo[n2 * 16 * LDB + ks * 16], LDB);
        }
#pragma unroll
        for (int m2 = 0; m2 < MT; m2++) {
            const int mt   = wid * MT + m2;
            const int yloc = mt >> 1;
            const int x0   = (mt & 1) * 16;
            const int ab   = ((yloc + dy) * 34 + x0 + dx) * CINPAD + cc * 16;
            wmma::fragment<wmma::matrix_a, 16, 16, 16, __nv_bfloat16,
                           wmma::row_major> a_hi, a_lo;
            wmma::load_matrix_sync(a_hi, &sA_hi[ab], CINPAD);
            wmma::load_matrix_sync(a_lo, &sA_lo[ab], CINPAD);
#pragma unroll
            for (int n2 = 0; n2 < NT; n2++) {
                wmma::mma_sync(acc_hh[m2][n2], a_hi, b_hi[n2], acc_hh[m2][n2]);
                wmma::mma_sync(acc_lh[m2][n2], a_lo, b_hi[n2], acc_lh[m2][n2]);
                wmma::mma_sync(acc_hl[m2][n2], a_hi, b_lo[n2], acc_hl[m2][n2]);
            }
        }
    }

    // ---- merge split terms + store ----
    float* optr = out + (size_t)n * COUT * HW + pix0;
#pragma unroll
    for (int m2 = 0; m2 < MT; m2++)
#pragma unroll
        for (int n2 = 0; n2 < NT; n2++) {
#pragma unroll
            for (int i = 0; i < acc_hh[m2][n2].num_elements; i++)
                acc_hh[m2][n2].x[i] += acc_lh[m2][n2].x[i] + acc_hl[m2][n2].x[i];
            wmma::store_matrix_sync(
                optr + n2 * 16 * HW + (wid * MT + m2) * 16,
                acc_hh[m2][n2], HW, wmma::mem_col_major);
        }
}

// ---------------------------------------------------------------------------
// Launch
// ---------------------------------------------------------------------------
extern "C" void kernel_launch(void* const* d_in, const int* in_sizes, int n_in,
                              void* d_out, int out_size) {
    const float* x     = (const float*)d_in[0];
    const void*  edges = (const void*)d_in[1];
    const float* w1    = (const float*)d_in[2];
    const float* b1    = (const float*)d_in[3];
    const float* w2    = (const float*)d_in[4];
    const float* b2    = (const float*)d_in[5];
    const float* w3    = (const float*)d_in[6];
    const float* b3    = (const float*)d_in[7];
    float*       out   = (float*)d_out;

    int E = in_sizes[1] / 3;
    if (E > EMAX) E = EMAX;

    float *neigh, *nonneigh, *h1, *h2;
    cudaGetSymbolAddress((void**)&neigh,    g_neigh);
    cudaGetSymbolAddress((void**)&nonneigh, g_nonneigh);
    cudaGetSymbolAddress((void**)&h1,       g_h1);
    cudaGetSymbolAddress((void**)&h2,       g_h2);
    __nv_bfloat16 *b1h, *b1l, *b2h, *b2l, *b3h, *b3l;
    cudaGetSymbolAddress((void**)&b1h, g_b1hi);
    cudaGetSymbolAddress((void**)&b1l, g_b1lo);
    cudaGetSymbolAddress((void**)&b2h, g_b2hi);
    cudaGetSymbolAddress((void**)&b2l, g_b2lo);
    cudaGetSymbolAddress((void**)&b3h, g_b3hi);
    cudaGetSymbolAddress((void**)&b3l, g_b3lo);

    probe_dtype_kernel<<<1, 1>>>(edges, E);

    csr_zero_kernel<<<(NN + 255) / 256, 256>>>();
    csr_count_kernel<<<(E + 255) / 256, 256>>>(edges, E);
    csr_scan_kernel<<<1, 1024>>>();
    csr_fill_kernel<<<(E + 255) / 256, 256>>>(edges, E);

    dim3 ggrid(NN, 2);
    gather_kernel<<<ggrid, 256>>>(x, neigh, nonneigh);

    prep_b_kernel<<<(32 * 432 + 255) / 256, 256>>>(w1, w2, w3);

    const int smem1 = 2 * (6 * 34 * 56) * 2 + 2 * (32 * 440) * 2 + 2048;  // 104064
    const int smem2 = 2 * (10 * 34 * 40) * 2 + 2 * (32 * 296) * 2 + 2048; //  94336
    const int smem3 = 2 * (10 * 34 * 40) * 2 + 2 * (16 * 296) * 2 + 1024; //  74368

    static bool attr_set = false;
    if (!attr_set) {
        cudaFuncSetAttribute((const void*)conv_shift_kernel<48, 56, 32, 4, 440, 27>,
                             cudaFuncAttributeMaxDynamicSharedMemorySize, smem1);
        cudaFuncSetAttribute((const void*)conv_shift_kernel<32, 40, 32, 8, 296, 18>,
                             cudaFuncAttributeMaxDynamicSharedMemorySize, smem2);
        cudaFuncSetAttribute((const void*)conv_shift_kernel<32, 40, 16, 8, 296, 18>,
                             cudaFuncAttributeMaxDynamicSharedMemorySize, smem3);
        attr_set = true;
    }

    conv_shift_kernel<48, 56, 32, 4, 440, 27><<<dim3(NN, 8), 256, smem1>>>(
        x, neigh, nonneigh, CC * HW, b1h, b1l, b1, h1);
    conv_shift_kernel<32, 40, 32, 8, 296, 18><<<dim3(NN, 4), 256, smem2>>>(
        h1, h1 + 16 * HW, nullptr, 32 * HW, b2h, b2l, b2, h2);
    conv_shift_kernel<32, 40, 16, 8, 296, 18><<<dim3(NN, 4), 256, smem3>>>(
        h2, h2 + 16 * HW, nullptr, 32 * HW, b3h, b3l, b3, out);
}

// round 9
// speedup vs baseline: 1.0904x; 1.0904x over previous
#include <cuda_runtime.h>
#include <cuda_bf16.h>
#include <mma.h>
#include <cstdint>

using namespace nvcuda;

// ---------------------------------------------------------------------------
// Problem constants
// ---------------------------------------------------------------------------
#define NN    2048         // nodes / batch
#define CC    16           // channels of x
#define HH    32
#define WW    32
#define HW    (HH*WW)      // 1024
#define FEAT  (CC*HW)      // 16384 floats per node
#define EMAX  16384

// Scratch (device globals; zero-initialized at module load)
__device__ float g_neigh   [NN * CC * HW];
__device__ float g_nonneigh[NN * CC * HW];
__device__ float g_h1      [NN * 32 * HW];
__device__ float g_h2      [NN * 32 * HW];
__device__ int   g_deg[NN];               // re-zeroed by scan_fill each call
__device__ int   g_off[NN + 1];
__device__ int   g_adj[2 * EMAX];         // peer | (0x10000 if rel>0)

// Pre-split weights (bf16 hi/lo), K-ordered: k = (tap*(CIN/16)+cc)*16 + j.
__device__ __align__(16) __nv_bfloat16 g_b1hi[32 * 440];
__device__ __align__(16) __nv_bfloat16 g_b1lo[32 * 440];
__device__ __align__(16) __nv_bfloat16 g_b2hi[32 * 296];
__device__ __align__(16) __nv_bfloat16 g_b2lo[32 * 296];
__device__ __align__(16) __nv_bfloat16 g_b3hi[16 * 296];
__device__ __align__(16) __nv_bfloat16 g_b3lo[16 * 296];

// ---------------------------------------------------------------------------
// Edge dtype: self-discriminating from edge 0. int32 data reinterpreted as
// int64 packs (a,rel) -> |value| >= 2^32 or negative (rel=+-1), so the
// plausibility test fails; genuine int64 edges pass.
// ---------------------------------------------------------------------------
__device__ __forceinline__ bool edges_are_64(const void* edges) {
    const long long* p = (const long long*)edges;
    long long a = p[0], r = p[1], b = p[2];
    return (a >= 0 && a < NN && b >= 0 && b < NN && (r == 1 || r == -1));
}

__device__ __forceinline__ void load_edge(const void* edges, bool is64, int e,
                                          int& a, int& rel, int& b) {
    if (is64) {
        const long long* p = (const long long*)edges;
        a = (int)p[3 * e + 0]; rel = (int)p[3 * e + 1]; b = (int)p[3 * e + 2];
    } else {
        const int* p = (const int*)edges;
        a = p[3 * e + 0]; rel = p[3 * e + 1]; b = p[3 * e + 2];
    }
}

// ---------------------------------------------------------------------------
// Launch 1: degree count (blocks [0, cntBlocks)) + weight split prep (rest).
// ---------------------------------------------------------------------------
__global__ void csr_count_prep_kernel(const void* edges, int E, int cntBlocks,
                                      const float* __restrict__ w1,
                                      const float* __restrict__ w2,
                                      const float* __restrict__ w3) {
    if ((int)blockIdx.x < cntBlocks) {
        int e = blockIdx.x * 256 + threadIdx.x;
        if (e >= E) return;
        bool is64 = edges_are_64(edges);
        int a, rel, b;
        load_edge(edges, is64, e, a, rel, b);
        if (a < 0 || a >= NN || b < 0 || b >= NN) return;
        atomicAdd(&g_deg[a], 1);
        atomicAdd(&g_deg[b], 1);
        return;
    }
    int idx = (blockIdx.x - cntBlocks) * 256 + threadIdx.x;
    if (idx < 32 * 432) {
        int co = idx / 432, k = idx - co * 432;
        int ks = k >> 4, j = k & 15;
        int tap = ks / 3, cc = ks - tap * 3;
        float v = w1[(size_t)(co * 48 + cc * 16 + j) * 9 + tap];
        __nv_bfloat16 bh = __float2bfloat16(v);
        g_b1hi[co * 440 + k] = bh;
        g_b1lo[co * 440 + k] = __float2bfloat16(v - __bfloat162float(bh));
    }
    if (idx < 32 * 288) {
        int co = idx / 288, k = idx - co * 288;
        int ks = k >> 4, j = k & 15;
        int tap = ks >> 1, cc = ks & 1;
        float v = w2[(size_t)(co * 32 + cc * 16 + j) * 9 + tap];
        __nv_bfloat16 bh = __float2bfloat16(v);
        g_b2hi[co * 296 + k] = bh;
        g_b2lo[co * 296 + k] = __float2bfloat16(v - __bfloat162float(bh));
    }
    if (idx < 16 * 288) {
        int co = idx / 288, k = idx - co * 288;
        int ks = k >> 4, j = k & 15;
        int tap = ks >> 1, cc = ks & 1;
        float v = w3[(size_t)(co * 32 + cc * 16 + j) * 9 + tap];
        __nv_bfloat16 bh = __float2bfloat16(v);
        g_b3hi[co * 296 + k] = bh;
        g_b3lo[co * 296 + k] = __float2bfloat16(v - __bfloat162float(bh));
    }
}

// ---------------------------------------------------------------------------
// Launch 2: single-block scan + adjacency fill. Cursors in smem.
// Re-zeroes g_deg for the next graph replay (determinism).
// ---------------------------------------------------------------------------
__global__ void __launch_bounds__(1024) csr_scan_fill_kernel(
        const void* edges, int E) {
    __shared__ int s[NN];
    __shared__ int scur[NN];
    int t = threadIdx.x;
    int d0 = g_deg[t], d1 = g_deg[t + 1024];
    g_deg[t] = 0; g_deg[t + 1024] = 0;
    s[t] = d0; s[t + 1024] = d1;
    __syncthreads();
    for (int d = 1; d < NN; d <<= 1) {
        int v0 = (t        >= d) ? s[t        - d] : 0;
        int v1 = (t + 1024 >= d) ? s[t + 1024 - d] : 0;
        __syncthreads();
        s[t]        += v0;
        s[t + 1024] += v1;
        __syncthreads();
    }
    g_off[t + 1]    = s[t];
    g_off[t + 1025] = s[t + 1024];
    if (t == 0) g_off[0] = 0;
    scur[t]        = (t == 0) ? 0 : s[t - 1];
    scur[t + 1024] = s[t + 1023];
    __syncthreads();

    bool is64 = edges_are_64(edges);
    for (int e = t; e < E; e += 1024) {
        int a, rel, b;
        load_edge(edges, is64, e, a, rel, b);
        if (a < 0 || a >= NN || b < 0 || b >= NN) continue;
        int flag = (rel > 0) ? 0x10000 : 0;
        int pa = atomicAdd(&scur[a], 1);
        g_adj[pa] = b | flag;
        int pb = atomicAdd(&scur[b], 1);
        g_adj[pb] = a | flag;
    }
}

// ---------------------------------------------------------------------------
// Launch 3: gather (CSR, no atomics). block = (node n, feature half h).
// ---------------------------------------------------------------------------
__global__ void __launch_bounds__(256) gather_kernel(
        const float* __restrict__ x,
        float* __restrict__ neigh,
        float* __restrict__ nonneigh) {
    const int n = blockIdx.x;
    const int h = blockIdx.y;
    const int t = threadIdx.x;

    float4 accN[8], accP[8];
#pragma unroll
    for (int j = 0; j < 8; j++) {
        accN[j] = make_float4(0.f, 0.f, 0.f, 0.f);
        accP[j] = make_float4(0.f, 0.f, 0.f, 0.f);
    }

    const int s = g_off[n], e = g_off[n + 1];
    const size_t base4h = (size_t)h * 2048;
    const float4* xb = (const float4*)x;

    for (int k = s; k < e; k++) {
        int ent = g_adj[k];
        int peer = ent & 0xFFFF;
        const float4* src = xb + (size_t)peer * (FEAT / 4) + base4h;
        if (ent & 0x10000) {
#pragma unroll
            for (int j = 0; j < 8; j++) {
                float4 v = src[t + 256 * j];
                accN[j].x += v.x; accN[j].y += v.y;
                accN[j].z += v.z; accN[j].w += v.w;
            }
        } else {
#pragma unroll
            for (int j = 0; j < 8; j++) {
                float4 v = src[t + 256 * j];
                accP[j].x += v.x; accP[j].y += v.y;
                accP[j].z += v.z; accP[j].w += v.w;
            }
        }
    }

    float4* dn = (float4*)neigh    + (size_t)n * (FEAT / 4) + base4h;
    float4* dp = (float4*)nonneigh + (size_t)n * (FEAT / 4) + base4h;
#pragma unroll
    for (int j = 0; j < 8; j++) {
        dn[t + 256 * j] = accN[j];
        dp[t + 256 * j] = accP[j];
    }
}

// ---------------------------------------------------------------------------
// Conv 3x3 as 9 shifted GEMMs (wmma bf16, split precision, fp32 accum).
// R7 form: single accumulator set, ks loop not unrolled.
// ---------------------------------------------------------------------------
template <int CIN, int CINPAD, int COUT, int ROWS, int LDB, int KSTEPS>
__global__ void __launch_bounds__(256)
conv_shift_kernel(const float* __restrict__ src0,
                  const float* __restrict__ src1,
                  const float* __restrict__ src2,
                  int imgStride,
                  const __nv_bfloat16* __restrict__ Bhi,
                  const __nv_bfloat16* __restrict__ Blo,
                  const float* __restrict__ bias,
                  float* __restrict__ out) {
    extern __shared__ __align__(16) char smem[];
    constexpr int TIN = (ROWS + 2) * 34;
    constexpr int ASZ = TIN * CINPAD;
    constexpr int BSZ = COUT * LDB;
    constexpr int NT  = COUT / 16;
    constexpr int MT  = ROWS / 4;
    constexpr int NCC = CIN / 16;

    __nv_bfloat16* sA_hi = (__nv_bfloat16*)smem;
    __nv_bfloat16* sA_lo = sA_hi + ASZ;
    __nv_bfloat16* sB_hi = sA_lo + ASZ;
    __nv_bfloat16* sB_lo = sB_hi + BSZ;
    float*         sBias = (float*)(sB_lo + BSZ);

    const int tid  = threadIdx.x;
    const int wid  = tid >> 5;
    const int n    = blockIdx.x;
    const int row0 = blockIdx.y * ROWS;
    const int pix0 = row0 * 32;

    // ---- B copy (global bf16 -> smem), uint4 ----
    {
        const uint4* g1 = (const uint4*)Bhi;
        const uint4* g2 = (const uint4*)Blo;
        uint4* s1 = (uint4*)sB_hi;
        uint4* s2 = (uint4*)sB_lo;
        constexpr int NB = BSZ * 2 / 16;
        for (int i = tid; i < NB; i += 256) { s1[i] = g1[i]; s2[i] = g2[i]; }
    }
    // ---- bias tile ----
    for (int i = tid; i < 16 * COUT; i += 256) sBias[i] = bias[i & (COUT - 1)];

    // ---- A staging: fp32 -> bf16 hi/lo, [pixel][cin] ----
    const float* p0 = src0 + (size_t)n * imgStride;
    const float* p1 = src1 ? src1 + (size_t)n * imgStride : p0;
    const float* p2 = src2 ? src2 + (size_t)n * imgStride : p0;
    for (int idx = tid; idx < CIN * TIN; idx += 256) {
        int cin = idx / TIN;
        int pix = idx - cin * TIN;
        int r = pix / 34, c = pix - r * 34;
        int y = row0 + r - 1, x = c - 1;
        float v = 0.f;
        if ((unsigned)y < HH && (unsigned)x < WW) {
            const float* sp = (cin < 16) ? p0 : (cin < 32) ? p1 : p2;
            v = sp[(cin & 15) * HW + y * WW + x];
        }
        __nv_bfloat16 bh = __float2bfloat16(v);
        sA_hi[pix * CINPAD + cin] = bh;
        sA_lo[pix * CINPAD + cin] = __float2bfloat16(v - __bfloat162float(bh));
    }
    __syncthreads();

    wmma::fragment<wmma::accumulator, 16, 16, 16, float> acc[MT][NT];
#pragma unroll
    for (int m2 = 0; m2 < MT; m2++)
#pragma unroll
        for (int n2 = 0; n2 < NT; n2++)
            wmma::load_matrix_sync(acc[m2][n2], sBias + n2 * 16, COUT,
                                   wmma::mem_row_major);

#pragma unroll 1
    for (int ks = 0; ks < KSTEPS; ks++) {
        const int tap = ks / NCC;
        const int cc  = ks - tap * NCC;
        const int dy  = tap / 3;
        const int dx  = tap - dy * 3;

        wmma::fragment<wmma::matrix_b, 16, 16, 16, __nv_bfloat16,
                       wmma::col_major> b_hi[NT], b_lo[NT];
#pragma unroll
        for (int n2 = 0; n2 < NT; n2++) {
            wmma::load_matrix_sync(b_hi[n2], &sB_hi[n2 * 16 * LDB + ks * 16], LDB);
            wmma::load_matrix_sync(b_lo[n2], &sB_lo[n2 * 16 * LDB + ks * 16], LDB);
        }
#pragma unroll
        for (int m2 = 0; m2 < MT; m2++) {
            const int mt   = wid * MT + m2;
            const int yloc = mt >> 1;
            const int x0   = (mt & 1) * 16;
            const int ab   = ((yloc + dy) * 34 + x0 + dx) * CINPAD + cc * 16;
            wmma::fragment<wmma::matrix_a, 16, 16, 16, __nv_bfloat16,
                           wmma::row_major> a_hi, a_lo;
            wmma::load_matrix_sync(a_hi, &sA_hi[ab], CINPAD);
            wmma::load_matrix_sync(a_lo, &sA_lo[ab], CINPAD);
#pragma unroll
            for (int n2 = 0; n2 < NT; n2++) {
                wmma::mma_sync(acc[m2][n2], a_hi, b_hi[n2], acc[m2][n2]);
                wmma::mma_sync(acc[m2][n2], a_lo, b_hi[n2], acc[m2][n2]);
                wmma::mma_sync(acc[m2][n2], a_hi, b_lo[n2], acc[m2][n2]);
            }
        }
    }

    float* optr = out + (size_t)n * COUT * HW + pix0;
#pragma unroll
    for (int m2 = 0; m2 < MT; m2++)
#pragma unroll
        for (int n2 = 0; n2 < NT; n2++)
            wmma::store_matrix_sync(
                optr + n2 * 16 * HW + (wid * MT + m2) * 16,
                acc[m2][n2], HW, wmma::mem_col_major);
}

// ---------------------------------------------------------------------------
// Launch: count_prep(1) -> scan_fill(2) -> gather(3) -> conv1(4) -> conv2(5)
//         -> conv3(6).  Slot #4 (ncu capture) = conv1.
// ---------------------------------------------------------------------------
extern "C" void kernel_launch(void* const* d_in, const int* in_sizes, int n_in,
                              void* d_out, int out_size) {
    const float* x     = (const float*)d_in[0];
    const void*  edges = (const void*)d_in[1];
    const float* w1    = (const float*)d_in[2];
    const float* b1    = (const float*)d_in[3];
    const float* w2    = (const float*)d_in[4];
    const float* b2    = (const float*)d_in[5];
    const float* w3    = (const float*)d_in[6];
    const float* b3    = (const float*)d_in[7];
    float*       out   = (float*)d_out;

    int E = in_sizes[1] / 3;
    if (E > EMAX) E = EMAX;

    float *neigh, *nonneigh, *h1, *h2;
    cudaGetSymbolAddress((void**)&neigh,    g_neigh);
    cudaGetSymbolAddress((void**)&nonneigh, g_nonneigh);
    cudaGetSymbolAddress((void**)&h1,       g_h1);
    cudaGetSymbolAddress((void**)&h2,       g_h2);
    __nv_bfloat16 *b1h, *b1l, *b2h, *b2l, *b3h, *b3l;
    cudaGetSymbolAddress((void**)&b1h, g_b1hi);
    cudaGetSymbolAddress((void**)&b1l, g_b1lo);
    cudaGetSymbolAddress((void**)&b2h, g_b2hi);
    cudaGetSymbolAddress((void**)&b2l, g_b2lo);
    cudaGetSymbolAddress((void**)&b3h, g_b3hi);
    cudaGetSymbolAddress((void**)&b3l, g_b3lo);

    const int cntBlocks  = (E + 255) / 256;
    const int prepBlocks = (32 * 432 + 255) / 256;
    csr_count_prep_kernel<<<cntBlocks + prepBlocks, 256>>>(
        edges, E, cntBlocks, w1, w2, w3);

    csr_scan_fill_kernel<<<1, 1024>>>(edges, E);

    dim3 ggrid(NN, 2);
    gather_kernel<<<ggrid, 256>>>(x, neigh, nonneigh);

    const int smem1 = 2 * (6 * 34 * 56) * 2 + 2 * (32 * 440) * 2 + 2048;  // 104064
    const int smem2 = 2 * (10 * 34 * 40) * 2 + 2 * (32 * 296) * 2 + 2048; //  94336
    const int smem3 = 2 * (10 * 34 * 40) * 2 + 2 * (16 * 296) * 2 + 1024; //  74368

    static bool attr_set = false;
    if (!attr_set) {
        cudaFuncSetAttribute((const void*)conv_shift_kernel<48, 56, 32, 4, 440, 27>,
                             cudaFuncAttributeMaxDynamicSharedMemorySize, smem1);
        cudaFuncSetAttribute((const void*)conv_shift_kernel<32, 40, 32, 8, 296, 18>,
                             cudaFuncAttributeMaxDynamicSharedMemorySize, smem2);
        cudaFuncSetAttribute((const void*)conv_shift_kernel<32, 40, 16, 8, 296, 18>,
                             cudaFuncAttributeMaxDynamicSharedMemorySize, smem3);
        attr_set = true;
    }

    conv_shift_kernel<48, 56, 32, 4, 440, 27><<<dim3(NN, 8), 256, smem1>>>(
        x, neigh, nonneigh, CC * HW, b1h, b1l, b1, h1);
    conv_shift_kernel<32, 40, 32, 8, 296, 18><<<dim3(NN, 4), 256, smem2>>>(
        h1, h1 + 16 * HW, nullptr, 32 * HW, b2h, b2l, b2, h2);
    conv_shift_kernel<32, 40, 16, 8, 296, 18><<<dim3(NN, 4), 256, smem3>>>(
        h2, h2 + 16 * HW, nullptr, 32 * HW, b3h, b3l, b3, out);
}

// round 14
// speedup vs baseline: 1.1494x; 1.0541x over previous
#include <cuda_runtime.h>
#include <cuda_bf16.h>
#include <mma.h>
#include <cstdint>

using namespace nvcuda;

// ---------------------------------------------------------------------------
// Problem constants
// ---------------------------------------------------------------------------
#define NN    2048
#define CC    16
#define HH    32
#define WW    32
#define HW    (HH*WW)      // 1024
#define FEAT  (CC*HW)      // 16384
#define EMAX  16384

typedef unsigned short u16;

// Scratch (device globals)
__device__ int  g_deg[NN];
__device__ int  g_off[NN + 1];
__device__ int  g_adj[2 * EMAX];

// bf16 hi/lo planes, layout [node][pixel 1024][cin]
__device__ __align__(16) u16 g_xT_hi[NN * HW * 16];
__device__ __align__(16) u16 g_xT_lo[NN * HW * 16];
__device__ __align__(16) u16 g_nT_hi[NN * HW * 16];
__device__ __align__(16) u16 g_nT_lo[NN * HW * 16];
__device__ __align__(16) u16 g_pT_hi[NN * HW * 16];
__device__ __align__(16) u16 g_pT_lo[NN * HW * 16];
__device__ __align__(16) u16 g_h1T_hi[NN * HW * 32];
__device__ __align__(16) u16 g_h1T_lo[NN * HW * 32];
__device__ __align__(16) u16 g_h2T_hi[NN * HW * 32];
__device__ __align__(16) u16 g_h2T_lo[NN * HW * 32];

// Pre-split weights (bf16 hi/lo), K-ordered: k = (tap*(CIN/16)+cc)*16 + j.
__device__ __align__(16) __nv_bfloat16 g_b1hi[32 * 440];
__device__ __align__(16) __nv_bfloat16 g_b1lo[32 * 440];
__device__ __align__(16) __nv_bfloat16 g_b2hi[32 * 296];
__device__ __align__(16) __nv_bfloat16 g_b2lo[32 * 296];
__device__ __align__(16) __nv_bfloat16 g_b3hi[16 * 296];
__device__ __align__(16) __nv_bfloat16 g_b3lo[16 * 296];

// ---------------------------------------------------------------------------
// bf16 hi/lo split helper
// ---------------------------------------------------------------------------
__device__ __forceinline__ void f2hilo(float v, u16& h, u16& l) {
    __nv_bfloat16 bh = __float2bfloat16(v);
    __nv_bfloat16 bl = __float2bfloat16(v - __bfloat162float(bh));
    union { __nv_bfloat16 b; u16 u; } ch, cl;
    ch.b = bh; cl.b = bl;
    h = ch.u; l = cl.u;
}

// ---------------------------------------------------------------------------
// Edge dtype: self-discriminating from edge 0.
// ---------------------------------------------------------------------------
__device__ __forceinline__ bool edges_are_64(const void* edges) {
    const long long* p = (const long long*)edges;
    long long a = p[0], r = p[1], b = p[2];
    return (a >= 0 && a < NN && b >= 0 && b < NN && (r == 1 || r == -1));
}

__device__ __forceinline__ void load_edge(const void* edges, bool is64, int e,
                                          int& a, int& rel, int& b) {
    if (is64) {
        const long long* p = (const long long*)edges;
        a = (int)p[3 * e + 0]; rel = (int)p[3 * e + 1]; b = (int)p[3 * e + 2];
    } else {
        const int* p = (const int*)edges;
        a = p[3 * e + 0]; rel = p[3 * e + 1]; b = p[3 * e + 2];
    }
}

// ---------------------------------------------------------------------------
// Launch 1: degree count + weight split prep (disjoint block ranges).
// ---------------------------------------------------------------------------
__global__ void csr_count_prep_kernel(const void* edges, int E, int cntBlocks,
                                      const float* __restrict__ w1,
                                      const float* __restrict__ w2,
                                      const float* __restrict__ w3) {
    if ((int)blockIdx.x < cntBlocks) {
        int e = blockIdx.x * 256 + threadIdx.x;
        if (e >= E) return;
        bool is64 = edges_are_64(edges);
        int a, rel, b;
        load_edge(edges, is64, e, a, rel, b);
        if (a < 0 || a >= NN || b < 0 || b >= NN) return;
        atomicAdd(&g_deg[a], 1);
        atomicAdd(&g_deg[b], 1);
        return;
    }
    int idx = (blockIdx.x - cntBlocks) * 256 + threadIdx.x;
    if (idx < 32 * 432) {
        int co = idx / 432, k = idx - co * 432;
        int ks = k >> 4, j = k & 15;
        int tap = ks / 3, cc = ks - tap * 3;
        float v = w1[(size_t)(co * 48 + cc * 16 + j) * 9 + tap];
        __nv_bfloat16 bh = __float2bfloat16(v);
        g_b1hi[co * 440 + k] = bh;
        g_b1lo[co * 440 + k] = __float2bfloat16(v - __bfloat162float(bh));
    }
    if (idx < 32 * 288) {
        int co = idx / 288, k = idx - co * 288;
        int ks = k >> 4, j = k & 15;
        int tap = ks >> 1, cc = ks & 1;
        float v = w2[(size_t)(co * 32 + cc * 16 + j) * 9 + tap];
        __nv_bfloat16 bh = __float2bfloat16(v);
        g_b2hi[co * 296 + k] = bh;
        g_b2lo[co * 296 + k] = __float2bfloat16(v - __bfloat162float(bh));
    }
    if (idx < 16 * 288) {
        int co = idx / 288, k = idx - co * 288;
        int ks = k >> 4, j = k & 15;
        int tap = ks >> 1, cc = ks & 1;
        float v = w3[(size_t)(co * 32 + cc * 16 + j) * 9 + tap];
        __nv_bfloat16 bh = __float2bfloat16(v);
        g_b3hi[co * 296 + k] = bh;
        g_b3lo[co * 296 + k] = __float2bfloat16(v - __bfloat162float(bh));
    }
}

// ---------------------------------------------------------------------------
// Launch 2: single-block scan + adjacency fill; re-zeroes g_deg.
// ---------------------------------------------------------------------------
__global__ void __launch_bounds__(1024) csr_scan_fill_kernel(
        const void* edges, int E) {
    __shared__ int s[NN];
    __shared__ int scur[NN];
    int t = threadIdx.x;
    int d0 = g_deg[t], d1 = g_deg[t + 1024];
    g_deg[t] = 0; g_deg[t + 1024] = 0;
    s[t] = d0; s[t + 1024] = d1;
    __syncthreads();
    for (int d = 1; d < NN; d <<= 1) {
        int v0 = (t        >= d) ? s[t        - d] : 0;
        int v1 = (t + 1024 >= d) ? s[t + 1024 - d] : 0;
        __syncthreads();
        s[t]        += v0;
        s[t + 1024] += v1;
        __syncthreads();
    }
    g_off[t + 1]    = s[t];
    g_off[t + 1025] = s[t + 1024];
    if (t == 0) g_off[0] = 0;
    scur[t]        = (t == 0) ? 0 : s[t - 1];
    scur[t + 1024] = s[t + 1023];
    __syncthreads();

    bool is64 = edges_are_64(edges);
    for (int e = t; e < E; e += 1024) {
        int a, rel, b;
        load_edge(edges, is64, e, a, rel, b);
        if (a < 0 || a >= NN || b < 0 || b >= NN) continue;
        int flag = (rel > 0) ? 0x10000 : 0;
        int pa = atomicAdd(&scur[a], 1);
        g_adj[pa] = b | flag;
        int pb = atomicAdd(&scur[b], 1);
        g_adj[pb] = a | flag;
    }
}

// ---------------------------------------------------------------------------
// Launch 3: gather + transpose + bf16 split.
// Block (node n, pixel half h): accumulates fp32 (exact), then emits
// neighT / nonneighT / xT bf16 hi/lo planes in [pixel][16] layout via smem.
// Thread t: cin base cb = (t>>7)*8, pixel quad tl = t&127 (4 pixels).
// ---------------------------------------------------------------------------
__device__ __forceinline__ void flush_tile(
        float4 (&acc)[8], float* st, int n, int h, int t, int cb, int tl,
        u16* __restrict__ outh, u16* __restrict__ outl) {
    __syncthreads();
#pragma unroll
    for (int j = 0; j < 8; j++)
        *(float4*)&st[(cb + j) * 516 + 4 * tl] = acc[j];
    __syncthreads();
    for (int pp = t; pp < 512; pp += 256) {
        u16 hb[16], lb[16];
#pragma unroll
        for (int c = 0; c < 16; c++)
            f2hilo(st[c * 516 + pp], hb[c], lb[c]);
        size_t o = ((size_t)n * HW + h * 512 + pp) * 16;
        ((uint4*)(outh + o))[0] = ((uint4*)hb)[0];
        ((uint4*)(outh + o))[1] = ((uint4*)hb)[1];
        ((uint4*)(outl + o))[0] = ((uint4*)lb)[0];
        ((uint4*)(outl + o))[1] = ((uint4*)lb)[1];
    }
}

__global__ void __launch_bounds__(256) gather_kernel(
        const float* __restrict__ x) {
    __shared__ float st[16 * 516];            // 33 KB
    const int n = blockIdx.x;
    const int h = blockIdx.y;
    const int t = threadIdx.x;
    const int tl = t & 127;
    const int cb = (t >> 7) * 8;

    float4 accN[8], accP[8];
#pragma unroll
    for (int j = 0; j < 8; j++) {
        accN[j] = make_float4(0.f, 0.f, 0.f, 0.f);
        accP[j] = make_float4(0.f, 0.f, 0.f, 0.f);
    }

    const float4* xb = (const float4*)x;
    const int boff = h * 128 + tl;
    const int s = g_off[n], e = g_off[n + 1];
    for (int k = s; k < e; k++) {
        int ent = g_adj[k];
        int peer = ent & 0xFFFF;
        const float4* src = xb + (size_t)peer * (FEAT / 4) + boff;
        if (ent & 0x10000) {
#pragma unroll
            for (int j = 0; j < 8; j++) {
                float4 v = src[(cb + j) * 256];
                accN[j].x += v.x; accN[j].y += v.y;
                accN[j].z += v.z; accN[j].w += v.w;
            }
        } else {
#pragma unroll
            for (int j = 0; j < 8; j++) {
                float4 v = src[(cb + j) * 256];
                accP[j].x += v.x; accP[j].y += v.y;
                accP[j].z += v.z; accP[j].w += v.w;
            }
        }
    }

    flush_tile(accN, st, n, h, t, cb, tl, g_nT_hi, g_nT_lo);
    flush_tile(accP, st, n, h, t, cb, tl, g_pT_hi, g_pT_lo);

    // own-x transpose pass
    float4 ax[8];
    const float4* mysrc = xb + (size_t)n * (FEAT / 4) + boff;
#pragma unroll
    for (int j = 0; j < 8; j++) ax[j] = mysrc[(cb + j) * 256];
    flush_tile(ax, st, n, h, t, cb, tl, g_xT_hi, g_xT_lo);
}

// ---------------------------------------------------------------------------
// Conv 3x3 as 9 shifted GEMMs (wmma bf16, split precision, fp32 accum).
// R9 row-major compute core. A staging = pure uint4 copies from bf16 planes
// in [pixel][cin] layout. WRITE_T: epilogue emits bf16 hi/lo [pixel][cout]
// via smem round-trip; else fp32 [cout][pixel] (final output).
// ---------------------------------------------------------------------------
template <int CIN, int CINPAD, int COUT, int ROWS, int LDB, int KSTEPS, bool WRITE_T>
__global__ void __launch_bounds__(256)
conv_shift_kernel(const u16* __restrict__ a0h, const u16* __restrict__ a0l,
                  const u16* __restrict__ a1h, const u16* __restrict__ a1l,
                  const u16* __restrict__ a2h, const u16* __restrict__ a2l,
                  const __nv_bfloat16* __restrict__ Bhi,
                  const __nv_bfloat16* __restrict__ Blo,
                  const float* __restrict__ bias,
                  float* __restrict__ out,
                  u16* __restrict__ outTh, u16* __restrict__ outTl) {
    extern __shared__ __align__(16) char smem[];
    constexpr int TIN  = (ROWS + 2) * 34;
    constexpr int ASZ  = TIN * CINPAD;
    constexpr int BSZ  = COUT * LDB;
    constexpr int NT   = COUT / 16;
    constexpr int MT   = ROWS / 4;
    constexpr int NCC  = CIN / 16;
    constexpr int PIXB = ROWS * 32;
    constexpr int LDT  = COUT + 4;

    __nv_bfloat16* sA_hi = (__nv_bfloat16*)smem;
    __nv_bfloat16* sA_lo = sA_hi + ASZ;
    __nv_bfloat16* sB_hi = sA_lo + ASZ;
    __nv_bfloat16* sB_lo = sB_hi + BSZ;
    float*         sBias = (float*)(sB_lo + BSZ);

    const int tid  = threadIdx.x;
    const int wid  = tid >> 5;
    const int n    = blockIdx.x;
    const int row0 = blockIdx.y * ROWS;
    const int pix0 = row0 * 32;

    // ---- B copy ----
    {
        const uint4* g1 = (const uint4*)Bhi;
        const uint4* g2 = (const uint4*)Blo;
        uint4* s1 = (uint4*)sB_hi;
        uint4* s2 = (uint4*)sB_lo;
        constexpr int NB = BSZ * 2 / 16;
        for (int i = tid; i < NB; i += 256) { s1[i] = g1[i]; s2[i] = g2[i]; }
    }
    // ---- bias tile ----
    for (int i = tid; i < 16 * COUT; i += 256) sBias[i] = bias[i & (COUT - 1)];

    // ---- A staging: uint4 copies (16 cin per unit) ----
    for (int u = tid; u < TIN * NCC; u += 256) {
        int pix  = u / NCC;
        int sidx = u - pix * NCC;
        int r = pix / 34, c = pix - r * 34;
        int y = row0 + r - 1, xx = c - 1;
        uint4* dh = (uint4*)(sA_hi + pix * CINPAD + sidx * 16);
        uint4* dl = (uint4*)(sA_lo + pix * CINPAD + sidx * 16);
        if ((unsigned)y < HH && (unsigned)xx < WW) {
            int gp = y * WW + xx;
            const u16 *sh, *sl;
            if (CIN == 48) {
                const u16* bh_ = (sidx == 0) ? a0h : (sidx == 1) ? a1h : a2h;
                const u16* bl_ = (sidx == 0) ? a0l : (sidx == 1) ? a1l : a2l;
                sh = bh_ + ((size_t)n * HW + gp) * 16;
                sl = bl_ + ((size_t)n * HW + gp) * 16;
            } else {
                sh = a0h + ((size_t)n * HW + gp) * 32 + sidx * 16;
                sl = a0l + ((size_t)n * HW + gp) * 32 + sidx * 16;
            }
            dh[0] = ((const uint4*)sh)[0]; dh[1] = ((const uint4*)sh)[1];
            dl[0] = ((const uint4*)sl)[0]; dl[1] = ((const uint4*)sl)[1];
        } else {
            uint4 z = make_uint4(0u, 0u, 0u, 0u);
            dh[0] = z; dh[1] = z; dl[0] = z; dl[1] = z;
        }
    }
    __syncthreads();

    wmma::fragment<wmma::accumulator, 16, 16, 16, float> acc[MT][NT];
#pragma unroll
    for (int m2 = 0; m2 < MT; m2++)
#pragma unroll
        for (int n2 = 0; n2 < NT; n2++)
            wmma::load_matrix_sync(acc[m2][n2], sBias + n2 * 16, COUT,
                                   wmma::mem_row_major);

#pragma unroll 1
    for (int ks = 0; ks < KSTEPS; ks++) {
        const int tap = ks / NCC;
        const int cc  = ks - tap * NCC;
        const int dy  = tap / 3;
        const int dx  = tap - dy * 3;

        wmma::fragment<wmma::matrix_b, 16, 16, 16, __nv_bfloat16,
                       wmma::col_major> b_hi[NT], b_lo[NT];
#pragma unroll
        for (int n2 = 0; n2 < NT; n2++) {
            wmma::load_matrix_sync(b_hi[n2], &sB_hi[n2 * 16 * LDB + ks * 16], LDB);
            wmma::load_matrix_sync(b_lo[n2], &sB_lo[n2 * 16 * LDB + ks * 16], LDB);
        }
#pragma unroll
        for (int m2 = 0; m2 < MT; m2++) {
            const int mt   = wid * MT + m2;
            const int yloc = mt >> 1;
            const int x0   = (mt & 1) * 16;
            const int ab   = ((yloc + dy) * 34 + x0 + dx) * CINPAD + cc * 16;
            wmma::fragment<wmma::matrix_a, 16, 16, 16, __nv_bfloat16,
                           wmma::row_major> a_hi, a_lo;
            wmma::load_matrix_sync(a_hi, &sA_hi[ab], CINPAD);
            wmma::load_matrix_sync(a_lo, &sA_lo[ab], CINPAD);
#pragma unroll
            for (int n2 = 0; n2 < NT; n2++) {
                wmma::mma_sync(acc[m2][n2], a_hi, b_hi[n2], acc[m2][n2]);
                wmma::mma_sync(acc[m2][n2], a_lo, b_hi[n2], acc[m2][n2]);
                wmma::mma_sync(acc[m2][n2], a_hi, b_lo[n2], acc[m2][n2]);
            }
        }
    }

    if (WRITE_T) {
        // epilogue: smem tile [PIXB][LDT] fp32 -> bf16 hi/lo [pixel][COUT]
        __syncthreads();
        float* sT = (float*)smem;
#pragma unroll
        for (int m2 = 0; m2 < MT; m2++)
#pragma unroll
            for (int n2 = 0; n2 < NT; n2++)
                wmma::store_matrix_sync(
                    sT + (size_t)(wid * MT + m2) * 16 * LDT + n2 * 16,
                    acc[m2][n2], LDT, wmma::mem_row_major);
        __syncthreads();
        for (int e2 = tid; e2 < PIXB * NT; e2 += 256) {
            int p  = e2 / NT;
            int hf = e2 - p * NT;
            u16 hb[16], lb[16];
#pragma unroll
            for (int i = 0; i < 16; i++)
                f2hilo(sT[p * LDT + hf * 16 + i], hb[i], lb[i]);
            size_t o = ((size_t)n * HW + pix0 + p) * COUT + hf * 16;
            ((uint4*)(outTh + o))[0] = ((uint4*)hb)[0];
            ((uint4*)(outTh + o))[1] = ((uint4*)hb)[1];
            ((uint4*)(outTl + o))[0] = ((uint4*)lb)[0];
            ((uint4*)(outTl + o))[1] = ((uint4*)lb)[1];
        }
    } else {
        float* optr = out + (size_t)n * COUT * HW + pix0;
#pragma unroll
        for (int m2 = 0; m2 < MT; m2++)
#pragma unroll
            for (int n2 = 0; n2 < NT; n2++)
                wmma::store_matrix_sync(
                    optr + n2 * 16 * HW + (wid * MT + m2) * 16,
                    acc[m2][n2], HW, wmma::mem_col_major);
    }
}

// ---------------------------------------------------------------------------
// Launch: count_prep(0) -> scan_fill(1) -> gather(2) -> conv1(3, profiled)
//         -> conv2(4) -> conv3(5).
// ---------------------------------------------------------------------------
extern "C" void kernel_launch(void* const* d_in, const int* in_sizes, int n_in,
                              void* d_out, int out_size) {
    const float* x     = (const float*)d_in[0];
    const void*  edges = (const void*)d_in[1];
    const float* w1    = (const float*)d_in[2];
    const float* b1    = (const float*)d_in[3];
    const float* w2    = (const float*)d_in[4];
    const float* b2    = (const float*)d_in[5];
    const float* w3    = (const float*)d_in[6];
    const float* b3    = (const float*)d_in[7];
    float*       out   = (float*)d_out;

    int E = in_sizes[1] / 3;
    if (E > EMAX) E = EMAX;

    u16 *xTh, *xTl, *nTh, *nTl, *pTh, *pTl, *h1h, *h1l, *h2h, *h2l;
    cudaGetSymbolAddress((void**)&xTh, g_xT_hi);
    cudaGetSymbolAddress((void**)&xTl, g_xT_lo);
    cudaGetSymbolAddress((void**)&nTh, g_nT_hi);
    cudaGetSymbolAddress((void**)&nTl, g_nT_lo);
    cudaGetSymbolAddress((void**)&pTh, g_pT_hi);
    cudaGetSymbolAddress((void**)&pTl, g_pT_lo);
    cudaGetSymbolAddress((void**)&h1h, g_h1T_hi);
    cudaGetSymbolAddress((void**)&h1l, g_h1T_lo);
    cudaGetSymbolAddress((void**)&h2h, g_h2T_hi);
    cudaGetSymbolAddress((void**)&h2l, g_h2T_lo);
    __nv_bfloat16 *b1h, *b1l, *b2h, *b2l, *b3h, *b3l;
    cudaGetSymbolAddress((void**)&b1h, g_b1hi);
    cudaGetSymbolAddress((void**)&b1l, g_b1lo);
    cudaGetSymbolAddress((void**)&b2h, g_b2hi);
    cudaGetSymbolAddress((void**)&b2l, g_b2lo);
    cudaGetSymbolAddress((void**)&b3h, g_b3hi);
    cudaGetSymbolAddress((void**)&b3l, g_b3lo);

    const int cntBlocks  = (E + 255) / 256;
    const int prepBlocks = (32 * 432 + 255) / 256;
    csr_count_prep_kernel<<<cntBlocks + prepBlocks, 256>>>(
        edges, E, cntBlocks, w1, w2, w3);

    csr_scan_fill_kernel<<<1, 1024>>>(edges, E);

    dim3 ggrid(NN, 2);
    gather_kernel<<<ggrid, 256>>>(x);

    // smem: 2*ASZ*2B + 2*BSZ*2B + bias (epilogue tile aliases sA region)
    const int smem1 = 2 * (6 * 34 * 56) * 2 + 2 * (32 * 440) * 2 + 2048;  // 104064
    const int smem2 = 2 * (10 * 34 * 40) * 2 + 2 * (32 * 296) * 2 + 2048; //  94336
    const int smem3 = 2 * (10 * 34 * 40) * 2 + 2 * (16 * 296) * 2 + 1024; //  74368

    static bool attr_set = false;
    if (!attr_set) {
        cudaFuncSetAttribute(
            (const void*)conv_shift_kernel<48, 56, 32, 4, 440, 27, true>,
            cudaFuncAttributeMaxDynamicSharedMemorySize, smem1);
        cudaFuncSetAttribute(
            (const void*)conv_shift_kernel<32, 40, 32, 8, 296, 18, true>,
            cudaFuncAttributeMaxDynamicSharedMemorySize, smem2);
        cudaFuncSetAttribute(
            (const void*)conv_shift_kernel<32, 40, 16, 8, 296, 18, false>,
            cudaFuncAttributeMaxDynamicSharedMemorySize, smem3);
        attr_set = true;
    }

    // conv1: [xT | neighT | nonneighT] (48ch) -> h1T
    conv_shift_kernel<48, 56, 32, 4, 440, 27, true><<<dim3(NN, 8), 256, smem1>>>(
        xTh, xTl, nTh, nTl, pTh, pTl, b1h, b1l, b1, nullptr, h1h, h1l);
    // conv2: h1T (32ch) -> h2T
    conv_shift_kernel<32, 40, 32, 8, 296, 18, true><<<dim3(NN, 4), 256, smem2>>>(
        h1h, h1l, nullptr, nullptr, nullptr, nullptr, b2h, b2l, b2,
        nullptr, h2h, h2l);
    // conv3: h2T (32ch) -> out fp32 [cout][pixel]
    conv_shift_kernel<32, 40, 16, 8, 296, 18, false><<<dim3(NN, 4), 256, smem3>>>(
        h2h, h2l, nullptr, nullptr, nullptr, nullptr, b3h, b3l, b3,
        out, nullptr, nullptr);
}

// round 15
// speedup vs baseline: 1.2222x; 1.0634x over previous
#include <cuda_runtime.h>
#include <cuda_bf16.h>
#include <mma.h>
#include <cstdint>

using namespace nvcuda;

// ---------------------------------------------------------------------------
// Problem constants
// ---------------------------------------------------------------------------
#define NN    2048
#define CC    16
#define HH    32
#define WW    32
#define HW    (HH*WW)      // 1024
#define FEAT  (CC*HW)      // 16384
#define EMAX  16384

typedef unsigned short u16;

// Scratch (device globals)
__device__ int  g_deg[NN];
__device__ int  g_off[NN + 1];
__device__ int  g_adj[2 * EMAX];

// bf16 hi/lo planes, layout [node][pixel 1024][cin]
__device__ __align__(16) u16 g_xT_hi[NN * HW * 16];
__device__ __align__(16) u16 g_xT_lo[NN * HW * 16];
__device__ __align__(16) u16 g_nT_hi[NN * HW * 16];
__device__ __align__(16) u16 g_nT_lo[NN * HW * 16];
__device__ __align__(16) u16 g_pT_hi[NN * HW * 16];
__device__ __align__(16) u16 g_pT_lo[NN * HW * 16];
__device__ __align__(16) u16 g_h1T_hi[NN * HW * 32];
__device__ __align__(16) u16 g_h1T_lo[NN * HW * 32];
__device__ __align__(16) u16 g_h2T_hi[NN * HW * 32];
__device__ __align__(16) u16 g_h2T_lo[NN * HW * 32];

// Pre-split weights (bf16 hi/lo), K-ordered: k = (tap*(CIN/16)+cc)*16 + j.
__device__ __align__(16) __nv_bfloat16 g_b1hi[32 * 440];
__device__ __align__(16) __nv_bfloat16 g_b1lo[32 * 440];
__device__ __align__(16) __nv_bfloat16 g_b2hi[32 * 296];
__device__ __align__(16) __nv_bfloat16 g_b2lo[32 * 296];
__device__ __align__(16) __nv_bfloat16 g_b3hi[16 * 296];
__device__ __align__(16) __nv_bfloat16 g_b3lo[16 * 296];

// ---------------------------------------------------------------------------
// bf16 hi/lo split helper
// ---------------------------------------------------------------------------
__device__ __forceinline__ void f2hilo(float v, u16& h, u16& l) {
    __nv_bfloat16 bh = __float2bfloat16(v);
    __nv_bfloat16 bl = __float2bfloat16(v - __bfloat162float(bh));
    union { __nv_bfloat16 b; u16 u; } ch, cl;
    ch.b = bh; cl.b = bl;
    h = ch.u; l = cl.u;
}

// ---------------------------------------------------------------------------
// Edge dtype: self-discriminating from edge 0.
// ---------------------------------------------------------------------------
__device__ __forceinline__ bool edges_are_64(const void* edges) {
    const long long* p = (const long long*)edges;
    long long a = p[0], r = p[1], b = p[2];
    return (a >= 0 && a < NN && b >= 0 && b < NN && (r == 1 || r == -1));
}

__device__ __forceinline__ void load_edge(const void* edges, bool is64, int e,
                                          int& a, int& rel, int& b) {
    if (is64) {
        const long long* p = (const long long*)edges;
        a = (int)p[3 * e + 0]; rel = (int)p[3 * e + 1]; b = (int)p[3 * e + 2];
    } else {
        const int* p = (const int*)edges;
        a = p[3 * e + 0]; rel = p[3 * e + 1]; b = p[3 * e + 2];
    }
}

// ---------------------------------------------------------------------------
// Launch 1: degree count + weight split prep (disjoint block ranges).
// ---------------------------------------------------------------------------
__global__ void csr_count_prep_kernel(const void* edges, int E, int cntBlocks,
                                      const float* __restrict__ w1,
                                      const float* __restrict__ w2,
                                      const float* __restrict__ w3) {
    if ((int)blockIdx.x < cntBlocks) {
        int e = blockIdx.x * 256 + threadIdx.x;
        if (e >= E) return;
        bool is64 = edges_are_64(edges);
        int a, rel, b;
        load_edge(edges, is64, e, a, rel, b);
        if (a < 0 || a >= NN || b < 0 || b >= NN) return;
        atomicAdd(&g_deg[a], 1);
        atomicAdd(&g_deg[b], 1);
        return;
    }
    int idx = (blockIdx.x - cntBlocks) * 256 + threadIdx.x;
    if (idx < 32 * 432) {
        int co = idx / 432, k = idx - co * 432;
        int ks = k >> 4, j = k & 15;
        int tap = ks / 3, cc = ks - tap * 3;
        float v = w1[(size_t)(co * 48 + cc * 16 + j) * 9 + tap];
        __nv_bfloat16 bh = __float2bfloat16(v);
        g_b1hi[co * 440 + k] = bh;
        g_b1lo[co * 440 + k] = __float2bfloat16(v - __bfloat162float(bh));
    }
    if (idx < 32 * 288) {
        int co = idx / 288, k = idx - co * 288;
        int ks = k >> 4, j = k & 15;
        int tap = ks >> 1, cc = ks & 1;
        float v = w2[(size_t)(co * 32 + cc * 16 + j) * 9 + tap];
        __nv_bfloat16 bh = __float2bfloat16(v);
        g_b2hi[co * 296 + k] = bh;
        g_b2lo[co * 296 + k] = __float2bfloat16(v - __bfloat162float(bh));
    }
    if (idx < 16 * 288) {
        int co = idx / 288, k = idx - co * 288;
        int ks = k >> 4, j = k & 15;
        int tap = ks >> 1, cc = ks & 1;
        float v = w3[(size_t)(co * 32 + cc * 16 + j) * 9 + tap];
        __nv_bfloat16 bh = __float2bfloat16(v);
        g_b3hi[co * 296 + k] = bh;
        g_b3lo[co * 296 + k] = __float2bfloat16(v - __bfloat162float(bh));
    }
}

// ---------------------------------------------------------------------------
// Launch 2: single-block scan + adjacency fill; re-zeroes g_deg.
// ---------------------------------------------------------------------------
__global__ void __launch_bounds__(1024) csr_scan_fill_kernel(
        const void* edges, int E) {
    __shared__ int s[NN];
    __shared__ int scur[NN];
    int t = threadIdx.x;
    int d0 = g_deg[t], d1 = g_deg[t + 1024];
    g_deg[t] = 0; g_deg[t + 1024] = 0;
    s[t] = d0; s[t + 1024] = d1;
    __syncthreads();
    for (int d = 1; d < NN; d <<= 1) {
        int v0 = (t        >= d) ? s[t        - d] : 0;
        int v1 = (t + 1024 >= d) ? s[t + 1024 - d] : 0;
        __syncthreads();
        s[t]        += v0;
        s[t + 1024] += v1;
        __syncthreads();
    }
    g_off[t + 1]    = s[t];
    g_off[t + 1025] = s[t + 1024];
    if (t == 0) g_off[0] = 0;
    scur[t]        = (t == 0) ? 0 : s[t - 1];
    scur[t + 1024] = s[t + 1023];
    __syncthreads();

    bool is64 = edges_are_64(edges);
    for (int e = t; e < E; e += 1024) {
        int a, rel, b;
        load_edge(edges, is64, e, a, rel, b);
        if (a < 0 || a >= NN || b < 0 || b >= NN) continue;
        int flag = (rel > 0) ? 0x10000 : 0;
        int pa = atomicAdd(&scur[a], 1);
        g_adj[pa] = b | flag;
        int pb = atomicAdd(&scur[b], 1);
        g_adj[pb] = a | flag;
    }
}

// ---------------------------------------------------------------------------
// Launch 3: gather + transpose + bf16 split.
// ---------------------------------------------------------------------------
__device__ __forceinline__ void flush_tile(
        float4 (&acc)[8], float* st, int n, int h, int t, int cb, int tl,
        u16* __restrict__ outh, u16* __restrict__ outl) {
    __syncthreads();
#pragma unroll
    for (int j = 0; j < 8; j++)
        *(float4*)&st[(cb + j) * 516 + 4 * tl] = acc[j];
    __syncthreads();
    for (int pp = t; pp < 512; pp += 256) {
        u16 hb[16], lb[16];
#pragma unroll
        for (int c = 0; c < 16; c++)
            f2hilo(st[c * 516 + pp], hb[c], lb[c]);
        size_t o = ((size_t)n * HW + h * 512 + pp) * 16;
        ((uint4*)(outh + o))[0] = ((uint4*)hb)[0];
        ((uint4*)(outh + o))[1] = ((uint4*)hb)[1];
        ((uint4*)(outl + o))[0] = ((uint4*)lb)[0];
        ((uint4*)(outl + o))[1] = ((uint4*)lb)[1];
    }
}

__global__ void __launch_bounds__(256) gather_kernel(
        const float* __restrict__ x) {
    __shared__ float st[16 * 516];            // 33 KB
    const int n = blockIdx.x;
    const int h = blockIdx.y;
    const int t = threadIdx.x;
    const int tl = t & 127;
    const int cb = (t >> 7) * 8;

    float4 accN[8], accP[8];
#pragma unroll
    for (int j = 0; j < 8; j++) {
        accN[j] = make_float4(0.f, 0.f, 0.f, 0.f);
        accP[j] = make_float4(0.f, 0.f, 0.f, 0.f);
    }

    const float4* xb = (const float4*)x;
    const int boff = h * 128 + tl;
    const int s = g_off[n], e = g_off[n + 1];
    for (int k = s; k < e; k++) {
        int ent = g_adj[k];
        int peer = ent & 0xFFFF;
        const float4* src = xb + (size_t)peer * (FEAT / 4) + boff;
        if (ent & 0x10000) {
#pragma unroll
            for (int j = 0; j < 8; j++) {
                float4 v = src[(cb + j) * 256];
                accN[j].x += v.x; accN[j].y += v.y;
                accN[j].z += v.z; accN[j].w += v.w;
            }
        } else {
#pragma unroll
            for (int j = 0; j < 8; j++) {
                float4 v = src[(cb + j) * 256];
                accP[j].x += v.x; accP[j].y += v.y;
                accP[j].z += v.z; accP[j].w += v.w;
            }
        }
    }

    flush_tile(accN, st, n, h, t, cb, tl, g_nT_hi, g_nT_lo);
    flush_tile(accP, st, n, h, t, cb, tl, g_pT_hi, g_pT_lo);

    float4 ax[8];
    const float4* mysrc = xb + (size_t)n * (FEAT / 4) + boff;
#pragma unroll
    for (int j = 0; j < 8; j++) ax[j] = mysrc[(cb + j) * 256];
    flush_tile(ax, st, n, h, t, cb, tl, g_xT_hi, g_xT_lo);
}

// ---------------------------------------------------------------------------
// Conv 3x3 as 9 shifted GEMMs (wmma bf16, split precision, fp32 accum).
// ROWS=16 tiles, 512 threads (16 warps, MT=2): B copied once per 16 rows,
// halo overhead 18/16, B-LDSM amortized over 2 m-tiles. 1 CTA/SM (smem),
// 16 warps/SM — same warp count as the old 2x256 config.
// ---------------------------------------------------------------------------
template <int CIN, int CINPAD, int COUT, int ROWS, int LDB, int KSTEPS, bool WRITE_T>
__global__ void __launch_bounds__(512)
conv_shift_kernel(const u16* __restrict__ a0h, const u16* __restrict__ a0l,
                  const u16* __restrict__ a1h, const u16* __restrict__ a1l,
                  const u16* __restrict__ a2h, const u16* __restrict__ a2l,
                  const __nv_bfloat16* __restrict__ Bhi,
                  const __nv_bfloat16* __restrict__ Blo,
                  const float* __restrict__ bias,
                  float* __restrict__ out,
                  u16* __restrict__ outTh, u16* __restrict__ outTl) {
    extern __shared__ __align__(16) char smem[];
    constexpr int THR  = 512;
    constexpr int TIN  = (ROWS + 2) * 34;
    constexpr int ASZ  = TIN * CINPAD;
    constexpr int BSZ  = COUT * LDB;
    constexpr int NT   = COUT / 16;
    constexpr int MT   = (ROWS * 2) / 16;      // m-tiles per warp (16 warps)
    constexpr int NCC  = CIN / 16;
    constexpr int PIXB = ROWS * 32;
    constexpr int LDT  = COUT + 4;

    __nv_bfloat16* sA_hi = (__nv_bfloat16*)smem;
    __nv_bfloat16* sA_lo = sA_hi + ASZ;
    __nv_bfloat16* sB_hi = sA_lo + ASZ;
    __nv_bfloat16* sB_lo = sB_hi + BSZ;
    float*         sBias = (float*)(sB_lo + BSZ);

    const int tid  = threadIdx.x;
    const int wid  = tid >> 5;
    const int n    = blockIdx.x;
    const int row0 = blockIdx.y * ROWS;
    const int pix0 = row0 * 32;

    // ---- B copy ----
    {
        const uint4* g1 = (const uint4*)Bhi;
        const uint4* g2 = (const uint4*)Blo;
        uint4* s1 = (uint4*)sB_hi;
        uint4* s2 = (uint4*)sB_lo;
        constexpr int NB = BSZ * 2 / 16;
        for (int i = tid; i < NB; i += THR) { s1[i] = g1[i]; s2[i] = g2[i]; }
    }
    // ---- bias tile ----
    for (int i = tid; i < 16 * COUT; i += THR) sBias[i] = bias[i & (COUT - 1)];

    // ---- A staging: uint4 copies (16 cin per unit) ----
    for (int u = tid; u < TIN * NCC; u += THR) {
        int pix  = u / NCC;
        int sidx = u - pix * NCC;
        int r = pix / 34, c = pix - r * 34;
        int y = row0 + r - 1, xx = c - 1;
        uint4* dh = (uint4*)(sA_hi + pix * CINPAD + sidx * 16);
        uint4* dl = (uint4*)(sA_lo + pix * CINPAD + sidx * 16);
        if ((unsigned)y < HH && (unsigned)xx < WW) {
            int gp = y * WW + xx;
            const u16 *sh, *sl;
            if (CIN == 48) {
                const u16* bh_ = (sidx == 0) ? a0h : (sidx == 1) ? a1h : a2h;
                const u16* bl_ = (sidx == 0) ? a0l : (sidx == 1) ? a1l : a2l;
                sh = bh_ + ((size_t)n * HW + gp) * 16;
                sl = bl_ + ((size_t)n * HW + gp) * 16;
            } else {
                sh = a0h + ((size_t)n * HW + gp) * 32 + sidx * 16;
                sl = a0l + ((size_t)n * HW + gp) * 32 + sidx * 16;
            }
            dh[0] = ((const uint4*)sh)[0]; dh[1] = ((const uint4*)sh)[1];
            dl[0] = ((const uint4*)sl)[0]; dl[1] = ((const uint4*)sl)[1];
        } else {
            uint4 z = make_uint4(0u, 0u, 0u, 0u);
            dh[0] = z; dh[1] = z; dl[0] = z; dl[1] = z;
        }
    }
    __syncthreads();

    wmma::fragment<wmma::accumulator, 16, 16, 16, float> acc[MT][NT];
#pragma unroll
    for (int m2 = 0; m2 < MT; m2++)
#pragma unroll
        for (int n2 = 0; n2 < NT; n2++)
            wmma::load_matrix_sync(acc[m2][n2], sBias + n2 * 16, COUT,
                                   wmma::mem_row_major);

#pragma unroll 1
    for (int ks = 0; ks < KSTEPS; ks++) {
        const int tap = ks / NCC;
        const int cc  = ks - tap * NCC;
        const int dy  = tap / 3;
        const int dx  = tap - dy * 3;

        wmma::fragment<wmma::matrix_b, 16, 16, 16, __nv_bfloat16,
                       wmma::col_major> b_hi[NT], b_lo[NT];
#pragma unroll
        for (int n2 = 0; n2 < NT; n2++) {
            wmma::load_matrix_sync(b_hi[n2], &sB_hi[n2 * 16 * LDB + ks * 16], LDB);
            wmma::load_matrix_sync(b_lo[n2], &sB_lo[n2 * 16 * LDB + ks * 16], LDB);
        }
#pragma unroll
        for (int m2 = 0; m2 < MT; m2++) {
            const int mt   = wid * MT + m2;
            const int yloc = mt >> 1;
            const int x0   = (mt & 1) * 16;
            const int ab   = ((yloc + dy) * 34 + x0 + dx) * CINPAD + cc * 16;
            wmma::fragment<wmma::matrix_a, 16, 16, 16, __nv_bfloat16,
                           wmma::row_major> a_hi, a_lo;
            wmma::load_matrix_sync(a_hi, &sA_hi[ab], CINPAD);
            wmma::load_matrix_sync(a_lo, &sA_lo[ab], CINPAD);
#pragma unroll
            for (int n2 = 0; n2 < NT; n2++) {
                wmma::mma_sync(acc[m2][n2], a_hi, b_hi[n2], acc[m2][n2]);
                wmma::mma_sync(acc[m2][n2], a_lo, b_hi[n2], acc[m2][n2]);
                wmma::mma_sync(acc[m2][n2], a_hi, b_lo[n2], acc[m2][n2]);
            }
        }
    }

    if (WRITE_T) {
        __syncthreads();
        float* sT = (float*)smem;
#pragma unroll
        for (int m2 = 0; m2 < MT; m2++)
#pragma unroll
            for (int n2 = 0; n2 < NT; n2++)
                wmma::store_matrix_sync(
                    sT + (size_t)(wid * MT + m2) * 16 * LDT + n2 * 16,
                    acc[m2][n2], LDT, wmma::mem_row_major);
        __syncthreads();
        for (int e2 = tid; e2 < PIXB * NT; e2 += THR) {
            int p  = e2 / NT;
            int hf = e2 - p * NT;
            u16 hb[16], lb[16];
#pragma unroll
            for (int i = 0; i < 16; i++)
                f2hilo(sT[p * LDT + hf * 16 + i], hb[i], lb[i]);
            size_t o = ((size_t)n * HW + pix0 + p) * COUT + hf * 16;
            ((uint4*)(outTh + o))[0] = ((uint4*)hb)[0];
            ((uint4*)(outTh + o))[1] = ((uint4*)hb)[1];
            ((uint4*)(outTl + o))[0] = ((uint4*)lb)[0];
            ((uint4*)(outTl + o))[1] = ((uint4*)lb)[1];
        }
    } else {
        float* optr = out + (size_t)n * COUT * HW + pix0;
#pragma unroll
        for (int m2 = 0; m2 < MT; m2++)
#pragma unroll
            for (int n2 = 0; n2 < NT; n2++)
                wmma::store_matrix_sync(
                    optr + n2 * 16 * HW + (wid * MT + m2) * 16,
                    acc[m2][n2], HW, wmma::mem_col_major);
    }
}

// ---------------------------------------------------------------------------
// Launch: count_prep(0) -> scan_fill(1) -> gather(2) -> conv1(3, profiled)
//         -> conv2(4) -> conv3(5).
// ---------------------------------------------------------------------------
extern "C" void kernel_launch(void* const* d_in, const int* in_sizes, int n_in,
                              void* d_out, int out_size) {
    const float* x     = (const float*)d_in[0];
    const void*  edges = (const void*)d_in[1];
    const float* w1    = (const float*)d_in[2];
    const float* b1    = (const float*)d_in[3];
    const float* w2    = (const float*)d_in[4];
    const float* b2    = (const float*)d_in[5];
    const float* w3    = (const float*)d_in[6];
    const float* b3    = (const float*)d_in[7];
    float*       out   = (float*)d_out;

    int E = in_sizes[1] / 3;
    if (E > EMAX) E = EMAX;

    u16 *xTh, *xTl, *nTh, *nTl, *pTh, *pTl, *h1h, *h1l, *h2h, *h2l;
    cudaGetSymbolAddress((void**)&xTh, g_xT_hi);
    cudaGetSymbolAddress((void**)&xTl, g_xT_lo);
    cudaGetSymbolAddress((void**)&nTh, g_nT_hi);
    cudaGetSymbolAddress((void**)&nTl, g_nT_lo);
    cudaGetSymbolAddress((void**)&pTh, g_pT_hi);
    cudaGetSymbolAddress((void**)&pTl, g_pT_lo);
    cudaGetSymbolAddress((void**)&h1h, g_h1T_hi);
    cudaGetSymbolAddress((void**)&h1l, g_h1T_lo);
    cudaGetSymbolAddress((void**)&h2h, g_h2T_hi);
    cudaGetSymbolAddress((void**)&h2l, g_h2T_lo);
    __nv_bfloat16 *b1h, *b1l, *b2h, *b2l, *b3h, *b3l;
    cudaGetSymbolAddress((void**)&b1h, g_b1hi);
    cudaGetSymbolAddress((void**)&b1l, g_b1lo);
    cudaGetSymbolAddress((void**)&b2h, g_b2hi);
    cudaGetSymbolAddress((void**)&b2l, g_b2lo);
    cudaGetSymbolAddress((void**)&b3h, g_b3hi);
    cudaGetSymbolAddress((void**)&b3l, g_b3lo);

    const int cntBlocks  = (E + 255) / 256;
    const int prepBlocks = (32 * 432 + 255) / 256;
    csr_count_prep_kernel<<<cntBlocks + prepBlocks, 256>>>(
        edges, E, cntBlocks, w1, w2, w3);

    csr_scan_fill_kernel<<<1, 1024>>>(edges, E);

    dim3 ggrid(NN, 2);
    gather_kernel<<<ggrid, 256>>>(x);

    // smem: 2*ASZ*2B + 2*BSZ*2B + bias
    const int smem1 = 2 * (18 * 34 * 56) * 2 + 2 * (32 * 440) * 2 + 2048; // 195456
    const int smem2 = 2 * (18 * 34 * 40) * 2 + 2 * (32 * 296) * 2 + 2048; // 137856
    const int smem3 = 2 * (18 * 34 * 40) * 2 + 2 * (16 * 296) * 2 + 1024; // 117888

    static bool attr_set = false;
    if (!attr_set) {
        cudaFuncSetAttribute(
            (const void*)conv_shift_kernel<48, 56, 32, 16, 440, 27, true>,
            cudaFuncAttributeMaxDynamicSharedMemorySize, smem1);
        cudaFuncSetAttribute(
            (const void*)conv_shift_kernel<32, 40, 32, 16, 296, 18, true>,
            cudaFuncAttributeMaxDynamicSharedMemorySize, smem2);
        cudaFuncSetAttribute(
            (const void*)conv_shift_kernel<32, 40, 16, 16, 296, 18, false>,
            cudaFuncAttributeMaxDynamicSharedMemorySize, smem3);
        attr_set = true;
    }

    // conv1: [xT | neighT | nonneighT] (48ch) -> h1T
    conv_shift_kernel<48, 56, 32, 16, 440, 27, true><<<dim3(NN, 2), 512, smem1>>>(
        xTh, xTl, nTh, nTl, pTh, pTl, b1h, b1l, b1, nullptr, h1h, h1l);
    // conv2: h1T (32ch) -> h2T
    conv_shift_kernel<32, 40, 32, 16, 296, 18, true><<<dim3(NN, 2), 512, smem2>>>(
        h1h, h1l, nullptr, nullptr, nullptr, nullptr, b2h, b2l, b2,
        nullptr, h2h, h2l);
    // conv3: h2T (32ch) -> out fp32 [cout][pixel]
    conv_shift_kernel<32, 40, 16, 16, 296, 18, false><<<dim3(NN, 2), 512, smem3>>>(
        h2h, h2l, nullptr, nullptr, nullptr, nullptr, b3h, b3l, b3,
        out, nullptr, nullptr);
}

// round 16
// speedup vs baseline: 1.2851x; 1.0514x over previous
#include <cuda_runtime.h>
#include <cuda_bf16.h>
#include <mma.h>
#include <cstdint>

using namespace nvcuda;

// ---------------------------------------------------------------------------
// Problem constants
// ---------------------------------------------------------------------------
#define NN    2048
#define CC    16
#define HH    32
#define WW    32
#define HW    (HH*WW)      // 1024
#define FEAT  (CC*HW)      // 16384
#define EMAX  16384

typedef unsigned short u16;

// Scratch (device globals)
__device__ int  g_deg[NN];
__device__ int  g_off[NN + 1];
__device__ int  g_adj[2 * EMAX];

// bf16 hi/lo planes, layout [node][pixel 1024][cin]
__device__ __align__(16) u16 g_xT_hi[NN * HW * 16];
__device__ __align__(16) u16 g_xT_lo[NN * HW * 16];
__device__ __align__(16) u16 g_nT_hi[NN * HW * 16];
__device__ __align__(16) u16 g_nT_lo[NN * HW * 16];
__device__ __align__(16) u16 g_pT_hi[NN * HW * 16];
__device__ __align__(16) u16 g_pT_lo[NN * HW * 16];
__device__ __align__(16) u16 g_h1T_hi[NN * HW * 32];
__device__ __align__(16) u16 g_h1T_lo[NN * HW * 32];
__device__ __align__(16) u16 g_h2T_hi[NN * HW * 32];
__device__ __align__(16) u16 g_h2T_lo[NN * HW * 32];

// Pre-split weights (bf16 hi/lo), K-ordered: k = (tap*(CIN/16)+cc)*16 + j.
__device__ __align__(16) __nv_bfloat16 g_b1hi[32 * 440];
__device__ __align__(16) __nv_bfloat16 g_b1lo[32 * 440];
__device__ __align__(16) __nv_bfloat16 g_b2hi[32 * 296];
__device__ __align__(16) __nv_bfloat16 g_b2lo[32 * 296];
__device__ __align__(16) __nv_bfloat16 g_b3hi[16 * 296];
__device__ __align__(16) __nv_bfloat16 g_b3lo[16 * 296];

// ---------------------------------------------------------------------------
// bf16 hi/lo split helper
// ---------------------------------------------------------------------------
__device__ __forceinline__ void f2hilo(float v, u16& h, u16& l) {
    __nv_bfloat16 bh = __float2bfloat16(v);
    __nv_bfloat16 bl = __float2bfloat16(v - __bfloat162float(bh));
    union { __nv_bfloat16 b; u16 u; } ch, cl;
    ch.b = bh; cl.b = bl;
    h = ch.u; l = cl.u;
}

// ---------------------------------------------------------------------------
// Edge dtype: self-discriminating from edge 0.
// ---------------------------------------------------------------------------
__device__ __forceinline__ bool edges_are_64(const void* edges) {
    const long long* p = (const long long*)edges;
    long long a = p[0], r = p[1], b = p[2];
    return (a >= 0 && a < NN && b >= 0 && b < NN && (r == 1 || r == -1));
}

__device__ __forceinline__ void load_edge(const void* edges, bool is64, int e,
                                          int& a, int& rel, int& b) {
    if (is64) {
        const long long* p = (const long long*)edges;
        a = (int)p[3 * e + 0]; rel = (int)p[3 * e + 1]; b = (int)p[3 * e + 2];
    } else {
        const int* p = (const int*)edges;
        a = p[3 * e + 0]; rel = p[3 * e + 1]; b = p[3 * e + 2];
    }
}

// ---------------------------------------------------------------------------
// Launch 1: degree count + weight split prep (disjoint block ranges).
// ---------------------------------------------------------------------------
__global__ void csr_count_prep_kernel(const void* edges, int E, int cntBlocks,
                                      const float* __restrict__ w1,
                                      const float* __restrict__ w2,
                                      const float* __restrict__ w3) {
    if ((int)blockIdx.x < cntBlocks) {
        int e = blockIdx.x * 256 + threadIdx.x;
        if (e >= E) return;
        bool is64 = edges_are_64(edges);
        int a, rel, b;
        load_edge(edges, is64, e, a, rel, b);
        if (a < 0 || a >= NN || b < 0 || b >= NN) return;
        atomicAdd(&g_deg[a], 1);
        atomicAdd(&g_deg[b], 1);
        return;
    }
    int idx = (blockIdx.x - cntBlocks) * 256 + threadIdx.x;
    if (idx < 32 * 432) {
        int co = idx / 432, k = idx - co * 432;
        int ks = k >> 4, j = k & 15;
        int tap = ks / 3, cc = ks - tap * 3;
        float v = w1[(size_t)(co * 48 + cc * 16 + j) * 9 + tap];
        __nv_bfloat16 bh = __float2bfloat16(v);
        g_b1hi[co * 440 + k] = bh;
        g_b1lo[co * 440 + k] = __float2bfloat16(v - __bfloat162float(bh));
    }
    if (idx < 32 * 288) {
        int co = idx / 288, k = idx - co * 288;
        int ks = k >> 4, j = k & 15;
        int tap = ks >> 1, cc = ks & 1;
        float v = w2[(size_t)(co * 32 + cc * 16 + j) * 9 + tap];
        __nv_bfloat16 bh = __float2bfloat16(v);
        g_b2hi[co * 296 + k] = bh;
        g_b2lo[co * 296 + k] = __float2bfloat16(v - __bfloat162float(bh));
    }
    if (idx < 16 * 288) {
        int co = idx / 288, k = idx - co * 288;
        int ks = k >> 4, j = k & 15;
        int tap = ks >> 1, cc = ks & 1;
        float v = w3[(size_t)(co * 32 + cc * 16 + j) * 9 + tap];
        __nv_bfloat16 bh = __float2bfloat16(v);
        g_b3hi[co * 296 + k] = bh;
        g_b3lo[co * 296 + k] = __float2bfloat16(v - __bfloat162float(bh));
    }
}

// ---------------------------------------------------------------------------
// Launch 2: single-block scan + adjacency fill; re-zeroes g_deg.
// ---------------------------------------------------------------------------
__global__ void __launch_bounds__(1024) csr_scan_fill_kernel(
        const void* edges, int E) {
    __shared__ int s[NN];
    __shared__ int scur[NN];
    int t = threadIdx.x;
    int d0 = g_deg[t], d1 = g_deg[t + 1024];
    g_deg[t] = 0; g_deg[t + 1024] = 0;
    s[t] = d0; s[t + 1024] = d1;
    __syncthreads();
    for (int d = 1; d < NN; d <<= 1) {
        int v0 = (t        >= d) ? s[t        - d] : 0;
        int v1 = (t + 1024 >= d) ? s[t + 1024 - d] : 0;
        __syncthreads();
        s[t]        += v0;
        s[t + 1024] += v1;
        __syncthreads();
    }
    g_off[t + 1]    = s[t];
    g_off[t + 1025] = s[t + 1024];
    if (t == 0) g_off[0] = 0;
    scur[t]        = (t == 0) ? 0 : s[t - 1];
    scur[t + 1024] = s[t + 1023];
    __syncthreads();

    bool is64 = edges_are_64(edges);
    for (int e = t; e < E; e += 1024) {
        int a, rel, b;
        load_edge(edges, is64, e, a, rel, b);
        if (a < 0 || a >= NN || b < 0 || b >= NN) continue;
        int flag = (rel > 0) ? 0x10000 : 0;
        int pa = atomicAdd(&scur[a], 1);
        g_adj[pa] = b | flag;
        int pb = atomicAdd(&scur[b], 1);
        g_adj[pb] = a | flag;
    }
}

// ---------------------------------------------------------------------------
// Launch 3: gather + transpose + bf16 split.
// ---------------------------------------------------------------------------
__device__ __forceinline__ void flush_tile(
        float4 (&acc)[8], float* st, int n, int h, int t, int cb, int tl,
        u16* __restrict__ outh, u16* __restrict__ outl) {
    __syncthreads();
#pragma unroll
    for (int j = 0; j < 8; j++)
        *(float4*)&st[(cb + j) * 516 + 4 * tl] = acc[j];
    __syncthreads();
    for (int pp = t; pp < 512; pp += 256) {
        u16 hb[16], lb[16];
#pragma unroll
        for (int c = 0; c < 16; c++)
            f2hilo(st[c * 516 + pp], hb[c], lb[c]);
        size_t o = ((size_t)n * HW + h * 512 + pp) * 16;
        ((uint4*)(outh + o))[0] = ((uint4*)hb)[0];
        ((uint4*)(outh + o))[1] = ((uint4*)hb)[1];
        ((uint4*)(outl + o))[0] = ((uint4*)lb)[0];
        ((uint4*)(outl + o))[1] = ((uint4*)lb)[1];
    }
}

__global__ void __launch_bounds__(256) gather_kernel(
        const float* __restrict__ x) {
    __shared__ float st[16 * 516];            // 33 KB
    const int n = blockIdx.x;
    const int h = blockIdx.y;
    const int t = threadIdx.x;
    const int tl = t & 127;
    const int cb = (t >> 7) * 8;

    float4 accN[8], accP[8];
#pragma unroll
    for (int j = 0; j < 8; j++) {
        accN[j] = make_float4(0.f, 0.f, 0.f, 0.f);
        accP[j] = make_float4(0.f, 0.f, 0.f, 0.f);
    }

    const float4* xb = (const float4*)x;
    const int boff = h * 128 + tl;
    const int s = g_off[n], e = g_off[n + 1];
    for (int k = s; k < e; k++) {
        int ent = g_adj[k];
        int peer = ent & 0xFFFF;
        const float4* src = xb + (size_t)peer * (FEAT / 4) + boff;
        if (ent & 0x10000) {
#pragma unroll
            for (int j = 0; j < 8; j++) {
                float4 v = src[(cb + j) * 256];
                accN[j].x += v.x; accN[j].y += v.y;
                accN[j].z += v.z; accN[j].w += v.w;
            }
        } else {
#pragma unroll
            for (int j = 0; j < 8; j++) {
                float4 v = src[(cb + j) * 256];
                accP[j].x += v.x; accP[j].y += v.y;
                accP[j].z += v.z; accP[j].w += v.w;
            }
        }
    }

    flush_tile(accN, st, n, h, t, cb, tl, g_nT_hi, g_nT_lo);
    flush_tile(accP, st, n, h, t, cb, tl, g_pT_hi, g_pT_lo);

    float4 ax[8];
    const float4* mysrc = xb + (size_t)n * (FEAT / 4) + boff;
#pragma unroll
    for (int j = 0; j < 8; j++) ax[j] = mysrc[(cb + j) * 256];
    flush_tile(ax, st, n, h, t, cb, tl, g_xT_hi, g_xT_lo);
}

// ---------------------------------------------------------------------------
// Conv 3x3 as 9 shifted GEMMs (wmma bf16, split precision, fp32 accum).
// ROWS=8, 256 threads (8 warps, MT=2). B staged in K-chunks of KCH=9 ksteps
// (LDBS=152 -> conflict-free), shrinking smem so 2-3 CTAs fit per SM:
// independent barrier domains overlap staging/epilogue with MMA.
// ---------------------------------------------------------------------------
template <int CIN, int CINPAD, int COUT, int LDBG, int KSTEPS, int KCH, bool WRITE_T>
__global__ void __launch_bounds__(256)
conv_shift_kernel(const u16* __restrict__ a0h, const u16* __restrict__ a0l,
                  const u16* __restrict__ a1h, const u16* __restrict__ a1l,
                  const u16* __restrict__ a2h, const u16* __restrict__ a2l,
                  const __nv_bfloat16* __restrict__ Bhi,
                  const __nv_bfloat16* __restrict__ Blo,
                  const float* __restrict__ bias,
                  float* __restrict__ out,
                  u16* __restrict__ outTh, u16* __restrict__ outTl) {
    extern __shared__ __align__(16) char smem[];
    constexpr int THR   = 256;
    constexpr int ROWS  = 8;
    constexpr int TIN   = (ROWS + 2) * 34;     // 340
    constexpr int ASZ   = TIN * CINPAD;
    constexpr int LDBS  = KCH * 16 + 8;        // 152
    constexpr int BSZC  = COUT * LDBS;
    constexpr int NT    = COUT / 16;
    constexpr int MT    = 2;                   // 8 warps x 2 = 16 m-tiles
    constexpr int NCC   = CIN / 16;
    constexpr int NCHK  = KSTEPS / KCH;
    constexpr int PIXB  = ROWS * 32;           // 256
    constexpr int LDT   = COUT + 4;

    __nv_bfloat16* sA_hi = (__nv_bfloat16*)smem;
    __nv_bfloat16* sA_lo = sA_hi + ASZ;
    __nv_bfloat16* sB_hi = sA_lo + ASZ;
    __nv_bfloat16* sB_lo = sB_hi + BSZC;
    float*         sBias = (float*)(sB_lo + BSZC);

    const int tid  = threadIdx.x;
    const int wid  = tid >> 5;
    const int n    = blockIdx.x;
    const int row0 = blockIdx.y * ROWS;
    const int pix0 = row0 * 32;

    // ---- bias tile ----
    for (int i = tid; i < 16 * COUT; i += THR) sBias[i] = bias[i & (COUT - 1)];

    // ---- A staging: uint4 copies (16 cin per unit) ----
    for (int u = tid; u < TIN * NCC; u += THR) {
        int pix  = u / NCC;
        int sidx = u - pix * NCC;
        int r = pix / 34, c = pix - r * 34;
        int y = row0 + r - 1, xx = c - 1;
        uint4* dh = (uint4*)(sA_hi + pix * CINPAD + sidx * 16);
        uint4* dl = (uint4*)(sA_lo + pix * CINPAD + sidx * 16);
        if ((unsigned)y < HH && (unsigned)xx < WW) {
            int gp = y * WW + xx;
            const u16 *sh, *sl;
            if (CIN == 48) {
                const u16* bh_ = (sidx == 0) ? a0h : (sidx == 1) ? a1h : a2h;
                const u16* bl_ = (sidx == 0) ? a0l : (sidx == 1) ? a1l : a2l;
                sh = bh_ + ((size_t)n * HW + gp) * 16;
                sl = bl_ + ((size_t)n * HW + gp) * 16;
            } else {
                sh = a0h + ((size_t)n * HW + gp) * 32 + sidx * 16;
                sl = a0l + ((size_t)n * HW + gp) * 32 + sidx * 16;
            }
            dh[0] = ((const uint4*)sh)[0]; dh[1] = ((const uint4*)sh)[1];
            dl[0] = ((const uint4*)sl)[0]; dl[1] = ((const uint4*)sl)[1];
        } else {
            uint4 z = make_uint4(0u, 0u, 0u, 0u);
            dh[0] = z; dh[1] = z; dl[0] = z; dl[1] = z;
        }
    }

    wmma::fragment<wmma::accumulator, 16, 16, 16, float> acc[MT][NT];
    __syncthreads();
#pragma unroll
    for (int m2 = 0; m2 < MT; m2++)
#pragma unroll
        for (int n2 = 0; n2 < NT; n2++)
            wmma::load_matrix_sync(acc[m2][n2], sBias + n2 * 16, COUT,
                                   wmma::mem_row_major);

#pragma unroll 1
    for (int chunk = 0; chunk < NCHK; chunk++) {
        // ---- stage B chunk: KCH ksteps (16 elems = 2 uint4 per unit) ----
        if (chunk > 0) __syncthreads();
        for (int i = tid; i < COUT * KCH * 2; i += THR) {
            int pl = (i >= COUT * KCH) ? 1 : 0;
            int r  = i - pl * COUT * KCH;
            int co = r / KCH, q = r - co * KCH;
            const __nv_bfloat16* gsrc = (pl ? Blo : Bhi)
                + (size_t)co * LDBG + chunk * KCH * 16 + q * 16;
            __nv_bfloat16* gdst = (pl ? sB_lo : sB_hi) + co * LDBS + q * 16;
            ((uint4*)gdst)[0] = ((const uint4*)gsrc)[0];
            ((uint4*)gdst)[1] = ((const uint4*)gsrc)[1];
        }
        __syncthreads();

#pragma unroll 1
        for (int ksl = 0; ksl < KCH; ksl++) {
            const int ks  = chunk * KCH + ksl;
            const int tap = ks / NCC;
            const int cc  = ks - tap * NCC;
            const int dy  = tap / 3;
            const int dx  = tap - dy * 3;

            wmma::fragment<wmma::matrix_b, 16, 16, 16, __nv_bfloat16,
                           wmma::col_major> b_hi[NT], b_lo[NT];
#pragma unroll
            for (int n2 = 0; n2 < NT; n2++) {
                wmma::load_matrix_sync(b_hi[n2],
                    &sB_hi[n2 * 16 * LDBS + ksl * 16], LDBS);
                wmma::load_matrix_sync(b_lo[n2],
                    &sB_lo[n2 * 16 * LDBS + ksl * 16], LDBS);
            }
#pragma unroll
            for (int m2 = 0; m2 < MT; m2++) {
                const int mt   = wid * MT + m2;
                const int yloc = mt >> 1;
                const int x0   = (mt & 1) * 16;
                const int ab   = ((yloc + dy) * 34 + x0 + dx) * CINPAD + cc * 16;
                wmma::fragment<wmma::matrix_a, 16, 16, 16, __nv_bfloat16,
                               wmma::row_major> a_hi, a_lo;
                wmma::load_matrix_sync(a_hi, &sA_hi[ab], CINPAD);
                wmma::load_matrix_sync(a_lo, &sA_lo[ab], CINPAD);
#pragma unroll
                for (int n2 = 0; n2 < NT; n2++) {
                    wmma::mma_sync(acc[m2][n2], a_hi, b_hi[n2], acc[m2][n2]);
                    wmma::mma_sync(acc[m2][n2], a_lo, b_hi[n2], acc[m2][n2]);
                    wmma::mma_sync(acc[m2][n2], a_hi, b_lo[n2], acc[m2][n2]);
                }
            }
        }
    }

    if (WRITE_T) {
        __syncthreads();
        float* sT = (float*)smem;
#pragma unroll
        for (int m2 = 0; m2 < MT; m2++)
#pragma unroll
            for (int n2 = 0; n2 < NT; n2++)
                wmma::store_matrix_sync(
                    sT + (size_t)(wid * MT + m2) * 16 * LDT + n2 * 16,
                    acc[m2][n2], LDT, wmma::mem_row_major);
        __syncthreads();
        for (int e2 = tid; e2 < PIXB * NT; e2 += THR) {
            int p  = e2 / NT;
            int hf = e2 - p * NT;
            u16 hb[16], lb[16];
#pragma unroll
            for (int i = 0; i < 16; i++)
                f2hilo(sT[p * LDT + hf * 16 + i], hb[i], lb[i]);
            size_t o = ((size_t)n * HW + pix0 + p) * COUT + hf * 16;
            ((uint4*)(outTh + o))[0] = ((uint4*)hb)[0];
            ((uint4*)(outTh + o))[1] = ((uint4*)hb)[1];
            ((uint4*)(outTl + o))[0] = ((uint4*)lb)[0];
            ((uint4*)(outTl + o))[1] = ((uint4*)lb)[1];
        }
    } else {
        float* optr = out + (size_t)n * COUT * HW + pix0;
#pragma unroll
        for (int m2 = 0; m2 < MT; m2++)
#pragma unroll
            for (int n2 = 0; n2 < NT; n2++)
                wmma::store_matrix_sync(
                    optr + n2 * 16 * HW + (wid * MT + m2) * 16,
                    acc[m2][n2], HW, wmma::mem_col_major);
    }
}

// ---------------------------------------------------------------------------
// Launch: count_prep(0) -> scan_fill(1) -> gather(2) -> conv1(3, profiled)
//         -> conv2(4) -> conv3(5).
// ---------------------------------------------------------------------------
extern "C" void kernel_launch(void* const* d_in, const int* in_sizes, int n_in,
                              void* d_out, int out_size) {
    const float* x     = (const float*)d_in[0];
    const void*  edges = (const void*)d_in[1];
    const float* w1    = (const float*)d_in[2];
    const float* b1    = (const float*)d_in[3];
    const float* w2    = (const float*)d_in[4];
    const float* b2    = (const float*)d_in[5];
    const float* w3    = (const float*)d_in[6];
    const float* b3    = (const float*)d_in[7];
    float*       out   = (float*)d_out;

    int E = in_sizes[1] / 3;
    if (E > EMAX) E = EMAX;

    u16 *xTh, *xTl, *nTh, *nTl, *pTh, *pTl, *h1h, *h1l, *h2h, *h2l;
    cudaGetSymbolAddress((void**)&xTh, g_xT_hi);
    cudaGetSymbolAddress((void**)&xTl, g_xT_lo);
    cudaGetSymbolAddress((void**)&nTh, g_nT_hi);
    cudaGetSymbolAddress((void**)&nTl, g_nT_lo);
    cudaGetSymbolAddress((void**)&pTh, g_pT_hi);
    cudaGetSymbolAddress((void**)&pTl, g_pT_lo);
    cudaGetSymbolAddress((void**)&h1h, g_h1T_hi);
    cudaGetSymbolAddress((void**)&h1l, g_h1T_lo);
    cudaGetSymbolAddress((void**)&h2h, g_h2T_hi);
    cudaGetSymbolAddress((void**)&h2l, g_h2T_lo);
    __nv_bfloat16 *b1h, *b1l, *b2h, *b2l, *b3h, *b3l;
    cudaGetSymbolAddress((void**)&b1h, g_b1hi);
    cudaGetSymbolAddress((void**)&b1l, g_b1lo);
    cudaGetSymbolAddress((void**)&b2h, g_b2hi);
    cudaGetSymbolAddress((void**)&b2l, g_b2lo);
    cudaGetSymbolAddress((void**)&b3h, g_b3hi);
    cudaGetSymbolAddress((void**)&b3l, g_b3lo);

    const int cntBlocks  = (E + 255) / 256;
    const int prepBlocks = (32 * 432 + 255) / 256;
    csr_count_prep_kernel<<<cntBlocks + prepBlocks, 256>>>(
        edges, E, cntBlocks, w1, w2, w3);

    csr_scan_fill_kernel<<<1, 1024>>>(edges, E);

    dim3 ggrid(NN, 2);
    gather_kernel<<<ggrid, 256>>>(x);

    // smem per CTA: 2*ASZ*2B + 2*BSZC*2B + bias
    // conv1: 2*(340*56)*2 + 2*(32*152)*2 + 2048 = 76160+19456+2048 =  97664
    // conv2: 2*(340*40)*2 + 2*(32*152)*2 + 2048 = 54400+19456+2048 =  75904
    // conv3: 2*(340*40)*2 + 2*(16*152)*2 + 1024 = 54400+ 9728+1024 =  65152
    const int smem1 = 97664;
    const int smem2 = 75904;
    const int smem3 = 65152;

    static bool attr_set = false;
    if (!attr_set) {
        cudaFuncSetAttribute(
            (const void*)conv_shift_kernel<48, 56, 32, 440, 27, 9, true>,
            cudaFuncAttributeMaxDynamicSharedMemorySize, smem1);
        cudaFuncSetAttribute(
            (const void*)conv_shift_kernel<32, 40, 32, 296, 18, 9, true>,
            cudaFuncAttributeMaxDynamicSharedMemorySize, smem2);
        cudaFuncSetAttribute(
            (const void*)conv_shift_kernel<32, 40, 16, 296, 18, 9, false>,
            cudaFuncAttributeMaxDynamicSharedMemorySize, smem3);
        attr_set = true;
    }

    // conv1: [xT | neighT | nonneighT] (48ch) -> h1T
    conv_shift_kernel<48, 56, 32, 440, 27, 9, true><<<dim3(NN, 4), 256, smem1>>>(
        xTh, xTl, nTh, nTl, pTh, pTl, b1h, b1l, b1, nullptr, h1h, h1l);
    // conv2: h1T (32ch) -> h2T
    conv_shift_kernel<32, 40, 32, 296, 18, 9, true><<<dim3(NN, 4), 256, smem2>>>(
        h1h, h1l, nullptr, nullptr, nullptr, nullptr, b2h, b2l, b2,
        nullptr, h2h, h2l);
    // conv3: h2T (32ch) -> out fp32 [cout][pixel]
    conv_shift_kernel<32, 40, 16, 296, 18, 9, false><<<dim3(NN, 4), 256, smem3>>>(
        h2h, h2l, nullptr, nullptr, nullptr, nullptr, b3h, b3l, b3,
        out, nullptr, nullptr);
}

// round 17
// speedup vs baseline: 1.3388x; 1.0418x over previous
#include <cuda_runtime.h>
#include <cuda_bf16.h>
#include <mma.h>
#include <cstdint>

using namespace nvcuda;

// ---------------------------------------------------------------------------
// Problem constants
// ---------------------------------------------------------------------------
#define NN    2048
#define CC    16
#define HH    32
#define WW    32
#define HW    (HH*WW)      // 1024
#define FEAT  (CC*HW)      // 16384
#define EMAX  16384

typedef unsigned short u16;

// Scratch (device globals)
__device__ int  g_deg[NN];
__device__ int  g_off[NN + 1];
__device__ int  g_adj[2 * EMAX];

// bf16 hi/lo planes, layout [node][pixel 1024][cin]
__device__ __align__(16) u16 g_xT_hi[NN * HW * 16];
__device__ __align__(16) u16 g_xT_lo[NN * HW * 16];
__device__ __align__(16) u16 g_nT_hi[NN * HW * 16];
__device__ __align__(16) u16 g_nT_lo[NN * HW * 16];
__device__ __align__(16) u16 g_pT_hi[NN * HW * 16];
__device__ __align__(16) u16 g_pT_lo[NN * HW * 16];
__device__ __align__(16) u16 g_h1T_hi[NN * HW * 32];
__device__ __align__(16) u16 g_h1T_lo[NN * HW * 32];
__device__ __align__(16) u16 g_h2T_hi[NN * HW * 32];
__device__ __align__(16) u16 g_h2T_lo[NN * HW * 32];

// Pre-split weights (bf16 hi/lo), K-ordered CC-MAJOR:
//   ks = cc*9 + tap, k = ks*16 + j, cin = cc*16 + j.
__device__ __align__(16) __nv_bfloat16 g_b1hi[32 * 440];
__device__ __align__(16) __nv_bfloat16 g_b1lo[32 * 440];
__device__ __align__(16) __nv_bfloat16 g_b2hi[32 * 296];
__device__ __align__(16) __nv_bfloat16 g_b2lo[32 * 296];
__device__ __align__(16) __nv_bfloat16 g_b3hi[16 * 296];
__device__ __align__(16) __nv_bfloat16 g_b3lo[16 * 296];

// ---------------------------------------------------------------------------
// bf16 hi/lo split helper
// ---------------------------------------------------------------------------
__device__ __forceinline__ void f2hilo(float v, u16& h, u16& l) {
    __nv_bfloat16 bh = __float2bfloat16(v);
    __nv_bfloat16 bl = __float2bfloat16(v - __bfloat162float(bh));
    union { __nv_bfloat16 b; u16 u; } ch, cl;
    ch.b = bh; cl.b = bl;
    h = ch.u; l = cl.u;
}

// ---------------------------------------------------------------------------
// Edge dtype: self-discriminating from edge 0.
// ---------------------------------------------------------------------------
__device__ __forceinline__ bool edges_are_64(const void* edges) {
    const long long* p = (const long long*)edges;
    long long a = p[0], r = p[1], b = p[2];
    return (a >= 0 && a < NN && b >= 0 && b < NN && (r == 1 || r == -1));
}

__device__ __forceinline__ void load_edge(const void* edges, bool is64, int e,
                                          int& a, int& rel, int& b) {
    if (is64) {
        const long long* p = (const long long*)edges;
        a = (int)p[3 * e + 0]; rel = (int)p[3 * e + 1]; b = (int)p[3 * e + 2];
    } else {
        const int* p = (const int*)edges;
        a = p[3 * e + 0]; rel = p[3 * e + 1]; b = p[3 * e + 2];
    }
}

// ---------------------------------------------------------------------------
// Launch 1: degree count + weight split prep (cc-major K order).
// ---------------------------------------------------------------------------
__global__ void csr_count_prep_kernel(const void* edges, int E, int cntBlocks,
                                      const float* __restrict__ w1,
                                      const float* __restrict__ w2,
                                      const float* __restrict__ w3) {
    if ((int)blockIdx.x < cntBlocks) {
        int e = blockIdx.x * 256 + threadIdx.x;
        if (e >= E) return;
        bool is64 = edges_are_64(edges);
        int a, rel, b;
        load_edge(edges, is64, e, a, rel, b);
        if (a < 0 || a >= NN || b < 0 || b >= NN) return;
        atomicAdd(&g_deg[a], 1);
        atomicAdd(&g_deg[b], 1);
        return;
    }
    int idx = (blockIdx.x - cntBlocks) * 256 + threadIdx.x;
    if (idx < 32 * 432) {
        int co = idx / 432, k = idx - co * 432;
        int ks = k >> 4, j = k & 15;
        int cc = ks / 9, tap = ks - cc * 9;
        float v = w1[(size_t)(co * 48 + cc * 16 + j) * 9 + tap];
        __nv_bfloat16 bh = __float2bfloat16(v);
        g_b1hi[co * 440 + k] = bh;
        g_b1lo[co * 440 + k] = __float2bfloat16(v - __bfloat162float(bh));
    }
    if (idx < 32 * 288) {
        int co = idx / 288, k = idx - co * 288;
        int ks = k >> 4, j = k & 15;
        int cc = ks / 9, tap = ks - cc * 9;
        float v = w2[(size_t)(co * 32 + cc * 16 + j) * 9 + tap];
        __nv_bfloat16 bh = __float2bfloat16(v);
        g_b2hi[co * 296 + k] = bh;
        g_b2lo[co * 296 + k] = __float2bfloat16(v - __bfloat162float(bh));
    }
    if (idx < 16 * 288) {
        int co = idx / 288, k = idx - co * 288;
        int ks = k >> 4, j = k & 15;
        int cc = ks / 9, tap = ks - cc * 9;
        float v = w3[(size_t)(co * 32 + cc * 16 + j) * 9 + tap];
        __nv_bfloat16 bh = __float2bfloat16(v);
        g_b3hi[co * 296 + k] = bh;
        g_b3lo[co * 296 + k] = __float2bfloat16(v - __bfloat162float(bh));
    }
}

// ---------------------------------------------------------------------------
// Launch 2: single-block scan + adjacency fill; re-zeroes g_deg.
// ---------------------------------------------------------------------------
__global__ void __launch_bounds__(1024) csr_scan_fill_kernel(
        const void* edges, int E) {
    __shared__ int s[NN];
    __shared__ int scur[NN];
    int t = threadIdx.x;
    int d0 = g_deg[t], d1 = g_deg[t + 1024];
    g_deg[t] = 0; g_deg[t + 1024] = 0;
    s[t] = d0; s[t + 1024] = d1;
    __syncthreads();
    for (int d = 1; d < NN; d <<= 1) {
        int v0 = (t        >= d) ? s[t        - d] : 0;
        int v1 = (t + 1024 >= d) ? s[t + 1024 - d] : 0;
        __syncthreads();
        s[t]        += v0;
        s[t + 1024] += v1;
        __syncthreads();
    }
    g_off[t + 1]    = s[t];
    g_off[t + 1025] = s[t + 1024];
    if (t == 0) g_off[0] = 0;
    scur[t]        = (t == 0) ? 0 : s[t - 1];
    scur[t + 1024] = s[t + 1023];
    __syncthreads();

    bool is64 = edges_are_64(edges);
    for (int e = t; e < E; e += 1024) {
        int a, rel, b;
        load_edge(edges, is64, e, a, rel, b);
        if (a < 0 || a >= NN || b < 0 || b >= NN) continue;
        int flag = (rel > 0) ? 0x10000 : 0;
        int pa = atomicAdd(&scur[a], 1);
        g_adj[pa] = b | flag;
        int pb = atomicAdd(&scur[b], 1);
        g_adj[pb] = a | flag;
    }
}

// ---------------------------------------------------------------------------
// Launch 3: gather + transpose + bf16 split.
// ---------------------------------------------------------------------------
__device__ __forceinline__ void flush_tile(
        float4 (&acc)[8], float* st, int n, int h, int t, int cb, int tl,
        u16* __restrict__ outh, u16* __restrict__ outl) {
    __syncthreads();
#pragma unroll
    for (int j = 0; j < 8; j++)
        *(float4*)&st[(cb + j) * 516 + 4 * tl] = acc[j];
    __syncthreads();
    for (int pp = t; pp < 512; pp += 256) {
        u16 hb[16], lb[16];
#pragma unroll
        for (int c = 0; c < 16; c++)
            f2hilo(st[c * 516 + pp], hb[c], lb[c]);
        size_t o = ((size_t)n * HW + h * 512 + pp) * 16;
        ((uint4*)(outh + o))[0] = ((uint4*)hb)[0];
        ((uint4*)(outh + o))[1] = ((uint4*)hb)[1];
        ((uint4*)(outl + o))[0] = ((uint4*)lb)[0];
        ((uint4*)(outl + o))[1] = ((uint4*)lb)[1];
    }
}

__global__ void __launch_bounds__(256) gather_kernel(
        const float* __restrict__ x) {
    __shared__ float st[16 * 516];            // 33 KB
    const int n = blockIdx.x;
    const int h = blockIdx.y;
    const int t = threadIdx.x;
    const int tl = t & 127;
    const int cb = (t >> 7) * 8;

    float4 accN[8], accP[8];
#pragma unroll
    for (int j = 0; j < 8; j++) {
        accN[j] = make_float4(0.f, 0.f, 0.f, 0.f);
        accP[j] = make_float4(0.f, 0.f, 0.f, 0.f);
    }

    const float4* xb = (const float4*)x;
    const int boff = h * 128 + tl;
    const int s = g_off[n], e = g_off[n + 1];
    for (int k = s; k < e; k++) {
        int ent = g_adj[k];
        int peer = ent & 0xFFFF;
        const float4* src = xb + (size_t)peer * (FEAT / 4) + boff;
        if (ent & 0x10000) {
#pragma unroll
            for (int j = 0; j < 8; j++) {
                float4 v = src[(cb + j) * 256];
                accN[j].x += v.x; accN[j].y += v.y;
                accN[j].z += v.z; accN[j].w += v.w;
            }
        } else {
#pragma unroll
            for (int j = 0; j < 8; j++) {
                float4 v = src[(cb + j) * 256];
                accP[j].x += v.x; accP[j].y += v.y;
                accP[j].z += v.z; accP[j].w += v.w;
            }
        }
    }

    flush_tile(accN, st, n, h, t, cb, tl, g_nT_hi, g_nT_lo);
    flush_tile(accP, st, n, h, t, cb, tl, g_pT_hi, g_pT_lo);

    float4 ax[8];
    const float4* mysrc = xb + (size_t)n * (FEAT / 4) + boff;
#pragma unroll
    for (int j = 0; j < 8; j++) ax[j] = mysrc[(cb + j) * 256];
    flush_tile(ax, st, n, h, t, cb, tl, g_xT_hi, g_xT_lo);
}

// ---------------------------------------------------------------------------
// Conv 3x3 as 9 shifted GEMMs (wmma bf16, split precision, fp32 accum).
// CC-CHUNKED: K consumed cc-major; per chunk, stage ONE 16-channel A slab
// (340 pix x 16 cin, pad 24) + its 9-kstep B slice, then 9 taps of MMA.
// smem ~53 KB -> 4 CTAs/SM (forced via __launch_bounds__(256,4)), 32 warps.
// ---------------------------------------------------------------------------
template <int CIN, int COUT, int LDBG, bool WRITE_T>
__global__ void __launch_bounds__(256, 4)
conv_shift_kernel(const u16* __restrict__ a0h, const u16* __restrict__ a0l,
                  const u16* __restrict__ a1h, const u16* __restrict__ a1l,
                  const u16* __restrict__ a2h, const u16* __restrict__ a2l,
                  const __nv_bfloat16* __restrict__ Bhi,
                  const __nv_bfloat16* __restrict__ Blo,
                  const float* __restrict__ bias,
                  float* __restrict__ out,
                  u16* __restrict__ outTh, u16* __restrict__ outTl) {
    extern __shared__ __align__(16) char smem[];
    constexpr int THR    = 256;
    constexpr int ROWS   = 8;
    constexpr int TIN    = (ROWS + 2) * 34;    // 340
    constexpr int CINPAD = 24;
    constexpr int ASZ    = TIN * CINPAD;       // 8160
    constexpr int LDBS   = 152;                // 9*16+8, conflict-free
    constexpr int BSZC   = COUT * LDBS;
    constexpr int NT     = COUT / 16;
    constexpr int MT     = 2;
    constexpr int NCC    = CIN / 16;
    constexpr int PIXB   = ROWS * 32;          // 256
    constexpr int LDT    = COUT + 4;

    __nv_bfloat16* sA_hi = (__nv_bfloat16*)smem;
    __nv_bfloat16* sA_lo = sA_hi + ASZ;
    __nv_bfloat16* sB_hi = sA_lo + ASZ;
    __nv_bfloat16* sB_lo = sB_hi + BSZC;
    float*         sBias = (float*)(sB_lo + BSZC);

    const int tid  = threadIdx.x;
    const int wid  = tid >> 5;
    const int n    = blockIdx.x;
    const int row0 = blockIdx.y * ROWS;
    const int pix0 = row0 * 32;

    // ---- bias tile ----
    for (int i = tid; i < 16 * COUT; i += THR) sBias[i] = bias[i & (COUT - 1)];
    __syncthreads();

    wmma::fragment<wmma::accumulator, 16, 16, 16, float> acc[MT][NT];
#pragma unroll
    for (int m2 = 0; m2 < MT; m2++)
#pragma unroll
        for (int n2 = 0; n2 < NT; n2++)
            wmma::load_matrix_sync(acc[m2][n2], sBias + n2 * 16, COUT,
                                   wmma::mem_row_major);

#pragma unroll 1
    for (int chunk = 0; chunk < NCC; chunk++) {
        if (chunk > 0) __syncthreads();        // drain prior chunk's reads

        // ---- stage A slab: 340 pixels x 16 cin (2 uint4 per pixel) ----
        for (int pix = tid; pix < TIN; pix += THR) {
            int r = pix / 34, c = pix - r * 34;
            int y = row0 + r - 1, xx = c - 1;
            uint4* dh = (uint4*)(sA_hi + pix * CINPAD);
            uint4* dl = (uint4*)(sA_lo + pix * CINPAD);
            if ((unsigned)y < HH && (unsigned)xx < WW) {
                int gp = y * WW + xx;
                const u16 *sh, *sl;
                if (CIN == 48) {
                    const u16* bh_ = (chunk == 0) ? a0h : (chunk == 1) ? a1h : a2h;
                    const u16* bl_ = (chunk == 0) ? a0l : (chunk == 1) ? a1l : a2l;
                    sh = bh_ + ((size_t)n * HW + gp) * 16;
                    sl = bl_ + ((size_t)n * HW + gp) * 16;
                } else {
                    sh = a0h + ((size_t)n * HW + gp) * 32 + chunk * 16;
                    sl = a0l + ((size_t)n * HW + gp) * 32 + chunk * 16;
                }
                dh[0] = ((const uint4*)sh)[0]; dh[1] = ((const uint4*)sh)[1];
                dl[0] = ((const uint4*)sl)[0]; dl[1] = ((const uint4*)sl)[1];
            } else {
                uint4 z = make_uint4(0u, 0u, 0u, 0u);
                dh[0] = z; dh[1] = z; dl[0] = z; dl[1] = z;
            }
        }
        // ---- stage B slice: 9 ksteps (16 elems = 2 uint4 per unit) ----
        for (int i = tid; i < COUT * 9 * 2; i += THR) {
            int pl = (i >= COUT * 9) ? 1 : 0;
            int r  = i - pl * COUT * 9;
            int co = r / 9, q = r - co * 9;
            const __nv_bfloat16* gsrc = (pl ? Blo : Bhi)
                + (size_t)co * LDBG + (chunk * 9 + q) * 16;
            __nv_bfloat16* gdst = (pl ? sB_lo : sB_hi) + co * LDBS + q * 16;
            ((uint4*)gdst)[0] = ((const uint4*)gsrc)[0];
            ((uint4*)gdst)[1] = ((const uint4*)gsrc)[1];
        }
        __syncthreads();

#pragma unroll 1
        for (int tap = 0; tap < 9; tap++) {
            const int dy = tap / 3;
            const int dx = tap - dy * 3;

            wmma::fragment<wmma::matrix_b, 16, 16, 16, __nv_bfloat16,
                           wmma::col_major> b_hi[NT], b_lo[NT];
#pragma unroll
            for (int n2 = 0; n2 < NT; n2++) {
                wmma::load_matrix_sync(b_hi[n2],
                    &sB_hi[n2 * 16 * LDBS + tap * 16], LDBS);
                wmma::load_matrix_sync(b_lo[n2],
                    &sB_lo[n2 * 16 * LDBS + tap * 16], LDBS);
            }
#pragma unroll
            for (int m2 = 0; m2 < MT; m2++) {
                const int mt   = wid * MT + m2;
                const int yloc = mt >> 1;
                const int x0   = (mt & 1) * 16;
                const int ab   = ((yloc + dy) * 34 + x0 + dx) * CINPAD;
                wmma::fragment<wmma::matrix_a, 16, 16, 16, __nv_bfloat16,
                               wmma::row_major> a_hi, a_lo;
                wmma::load_matrix_sync(a_hi, &sA_hi[ab], CINPAD);
                wmma::load_matrix_sync(a_lo, &sA_lo[ab], CINPAD);
#pragma unroll
                for (int n2 = 0; n2 < NT; n2++) {
                    wmma::mma_sync(acc[m2][n2], a_hi, b_hi[n2], acc[m2][n2]);
                    wmma::mma_sync(acc[m2][n2], a_lo, b_hi[n2], acc[m2][n2]);
                    wmma::mma_sync(acc[m2][n2], a_hi, b_lo[n2], acc[m2][n2]);
                }
            }
        }
    }

    if (WRITE_T) {
        __syncthreads();
        float* sT = (float*)smem;
#pragma unroll
        for (int m2 = 0; m2 < MT; m2++)
#pragma unroll
            for (int n2 = 0; n2 < NT; n2++)
                wmma::store_matrix_sync(
                    sT + (size_t)(wid * MT + m2) * 16 * LDT + n2 * 16,
                    acc[m2][n2], LDT, wmma::mem_row_major);
        __syncthreads();
        for (int e2 = tid; e2 < PIXB * NT; e2 += THR) {
            int p  = e2 / NT;
            int hf = e2 - p * NT;
            u16 hb[16], lb[16];
#pragma unroll
            for (int i = 0; i < 16; i++)
                f2hilo(sT[p * LDT + hf * 16 + i], hb[i], lb[i]);
            size_t o = ((size_t)n * HW + pix0 + p) * COUT + hf * 16;
            ((uint4*)(outTh + o))[0] = ((uint4*)hb)[0];
            ((uint4*)(outTh + o))[1] = ((uint4*)hb)[1];
            ((uint4*)(outTl + o))[0] = ((uint4*)lb)[0];
            ((uint4*)(outTl + o))[1] = ((uint4*)lb)[1];
        }
    } else {
        float* optr = out + (size_t)n * COUT * HW + pix0;
#pragma unroll
        for (int m2 = 0; m2 < MT; m2++)
#pragma unroll
            for (int n2 = 0; n2 < NT; n2++)
                wmma::store_matrix_sync(
                    optr + n2 * 16 * HW + (wid * MT + m2) * 16,
                    acc[m2][n2], HW, wmma::mem_col_major);
    }
}

// ---------------------------------------------------------------------------
// Launch: count_prep(0) -> scan_fill(1) -> gather(2) -> conv1(3, profiled)
//         -> conv2(4) -> conv3(5).
// ---------------------------------------------------------------------------
extern "C" void kernel_launch(void* const* d_in, const int* in_sizes, int n_in,
                              void* d_out, int out_size) {
    const float* x     = (const float*)d_in[0];
    const void*  edges = (const void*)d_in[1];
    const float* w1    = (const float*)d_in[2];
    const float* b1    = (const float*)d_in[3];
    const float* w2    = (const float*)d_in[4];
    const float* b2    = (const float*)d_in[5];
    const float* w3    = (const float*)d_in[6];
    const float* b3    = (const float*)d_in[7];
    float*       out   = (float*)d_out;

    int E = in_sizes[1] / 3;
    if (E > EMAX) E = EMAX;

    u16 *xTh, *xTl, *nTh, *nTl, *pTh, *pTl, *h1h, *h1l, *h2h, *h2l;
    cudaGetSymbolAddress((void**)&xTh, g_xT_hi);
    cudaGetSymbolAddress((void**)&xTl, g_xT_lo);
    cudaGetSymbolAddress((void**)&nTh, g_nT_hi);
    cudaGetSymbolAddress((void**)&nTl, g_nT_lo);
    cudaGetSymbolAddress((void**)&pTh, g_pT_hi);
    cudaGetSymbolAddress((void**)&pTl, g_pT_lo);
    cudaGetSymbolAddress((void**)&h1h, g_h1T_hi);
    cudaGetSymbolAddress((void**)&h1l, g_h1T_lo);
    cudaGetSymbolAddress((void**)&h2h, g_h2T_hi);
    cudaGetSymbolAddress((void**)&h2l, g_h2T_lo);
    __nv_bfloat16 *b1h, *b1l, *b2h, *b2l, *b3h, *b3l;
    cudaGetSymbolAddress((void**)&b1h, g_b1hi);
    cudaGetSymbolAddress((void**)&b1l, g_b1lo);
    cudaGetSymbolAddress((void**)&b2h, g_b2hi);
    cudaGetSymbolAddress((void**)&b2l, g_b2lo);
    cudaGetSymbolAddress((void**)&b3h, g_b3hi);
    cudaGetSymbolAddress((void**)&b3l, g_b3lo);

    const int cntBlocks  = (E + 255) / 256;
    const int prepBlocks = (32 * 432 + 255) / 256;
    csr_count_prep_kernel<<<cntBlocks + prepBlocks, 256>>>(
        edges, E, cntBlocks, w1, w2, w3);

    csr_scan_fill_kernel<<<1, 1024>>>(edges, E);

    dim3 ggrid(NN, 2);
    gather_kernel<<<ggrid, 256>>>(x);

    // smem per CTA: 2*8160*2 + 2*(COUT*152)*2 + bias
    // conv1/2: 32640 + 19456 + 2048 = 54144
    // conv3:   32640 +  9728 + 1024 = 43392
    const int smem1 = 54144;
    const int smem2 = 54144;
    const int smem3 = 43392;

    static bool attr_set = false;
    if (!attr_set) {
        cudaFuncSetAttribute(
            (const void*)conv_shift_kernel<48, 32, 440, true>,
            cudaFuncAttributeMaxDynamicSharedMemorySize, smem1);
        cudaFuncSetAttribute(
            (const void*)conv_shift_kernel<32, 32, 296, true>,
            cudaFuncAttributeMaxDynamicSharedMemorySize, smem2);
        cudaFuncSetAttribute(
            (const void*)conv_shift_kernel<32, 16, 296, false>,
            cudaFuncAttributeMaxDynamicSharedMemorySize, smem3);
        attr_set = true;
    }

    // conv1: [xT | neighT | nonneighT] (48ch) -> h1T
    conv_shift_kernel<48, 32, 440, true><<<dim3(NN, 4), 256, smem1>>>(
        xTh, xTl, nTh, nTl, pTh, pTl, b1h, b1l, b1, nullptr, h1h, h1l);
    // conv2: h1T (32ch) -> h2T
    conv_shift_kernel<32, 32, 296, true><<<dim3(NN, 4), 256, smem2>>>(
        h1h, h1l, nullptr, nullptr, nullptr, nullptr, b2h, b2l, b2,
        nullptr, h2h, h2l);
    // conv3: h2T (32ch) -> out fp32 [cout][pixel]
    conv_shift_kernel<32, 16, 296, false><<<dim3(NN, 4), 256, smem3>>>(
        h2h, h2l, nullptr, nullptr, nullptr, nullptr, b3h, b3l, b3,
        out, nullptr, nullptr);
}